// round 1
// baseline (speedup 1.0000x reference)
#include <cuda_runtime.h>
#include <math.h>

#define B_    2
#define S_    4096
#define T_    8192
#define IN_   1280
#define D_    768
#define H_    12
#define HD_   64
#define BS_   64
#define NB_   64
#define FF_   3072
#define L_    12
#define TGT_  1024

// ---------------- scratch (no allocations allowed) ----------------
__device__ float g_h[T_ * D_];
__device__ float g_q[T_ * D_];
__device__ float g_k[T_ * D_];
__device__ float g_v[T_ * D_];
__device__ float g_ctx[T_ * D_];
__device__ float g_tmp[T_ * D_];
__device__ float g_ff[T_ * FF_];
__device__ float g_cls[2 * 512];
__device__ int   g_gi[NB_ * 64];
__device__ int   g_gicnt[NB_];

// ---------------- gather-list construction ----------------
__global__ void build_gi_kernel(const int* __restrict__ rb) {
    int n = threadIdx.x;
    if (n >= NB_) return;
    if (n == 0 || n == NB_ - 1) {
        g_gicnt[n] = 64;
        for (int j = 0; j < 64; ++j) g_gi[n * 64 + j] = j;
    } else {
        g_gicnt[n] = 8;
        int* p = g_gi + n * 64;
        p[0] = 0; p[1] = n - 1; p[2] = n; p[3] = n + 1; p[4] = NB_ - 1;
        p[5] = rb[n * 3 + 0]; p[6] = rb[n * 3 + 1]; p[7] = rb[n * 3 + 2];
    }
}

// ---------------- generic SGEMM: C = A[M,K] @ W[K,N] + bias (+res)(+gelu) ----------------
template<bool GELU, bool RES>
__global__ __launch_bounds__(256) void sgemm_kernel(
    const float* __restrict__ A, const float* __restrict__ W,
    const float* __restrict__ bias, const float* __restrict__ res,
    float* __restrict__ C, int M, int N, int K)
{
    __shared__ float As[8][128];
    __shared__ float Bs[8][128];
    const int tid = threadIdx.x;
    const int tx = tid & 15, ty = tid >> 4;
    const int m0 = blockIdx.y * 128, n0 = blockIdx.x * 128;

    float acc[8][8];
#pragma unroll
    for (int i = 0; i < 8; ++i)
#pragma unroll
        for (int j = 0; j < 8; ++j) acc[i][j] = 0.f;

    const int arow = tid >> 1, acol = (tid & 1) * 4;
    const int brow = tid >> 5, bcol = (tid & 31) * 4;
    const float* Aptr = A + (size_t)(m0 + arow) * K + acol;
    const float* Wptr = W + (size_t)brow * N + n0 + bcol;

    for (int k0 = 0; k0 < K; k0 += 8) {
        float4 av = *(const float4*)(Aptr + k0);
        float4 bv = *(const float4*)(Wptr + (size_t)k0 * N);
        __syncthreads();
        As[acol + 0][arow] = av.x;
        As[acol + 1][arow] = av.y;
        As[acol + 2][arow] = av.z;
        As[acol + 3][arow] = av.w;
        *(float4*)&Bs[brow][bcol] = bv;
        __syncthreads();
#pragma unroll
        for (int kk = 0; kk < 8; ++kk) {
            float a[8], b[8];
            *(float4*)(a)     = *(const float4*)&As[kk][ty * 8];
            *(float4*)(a + 4) = *(const float4*)&As[kk][ty * 8 + 4];
            *(float4*)(b)     = *(const float4*)&Bs[kk][tx * 8];
            *(float4*)(b + 4) = *(const float4*)&Bs[kk][tx * 8 + 4];
#pragma unroll
            for (int i = 0; i < 8; ++i)
#pragma unroll
                for (int j = 0; j < 8; ++j) acc[i][j] += a[i] * b[j];
        }
    }

#pragma unroll
    for (int i = 0; i < 8; ++i) {
        int row = m0 + ty * 8 + i;
        float* crow = C + (size_t)row * N + n0 + tx * 8;
        const float* rrow = RES ? (res + (size_t)row * N + n0 + tx * 8) : nullptr;
#pragma unroll
        for (int j = 0; j < 8; ++j) {
            float v = acc[i][j] + bias[n0 + tx * 8 + j];
            if (RES) v += rrow[j];
            if (GELU) {
                float u = v;
                v = 0.5f * u * (1.0f + tanhf(0.7978845608028654f * (u + 0.044715f * u * u * u)));
            }
            crow[j] = v;
        }
    }
}

// ---------------- LayerNorm (optionally fused with +pos_emb+tok_emb) ----------------
__global__ __launch_bounds__(256) void ln_kernel(
    const float* __restrict__ in, const float* __restrict__ gamma,
    const float* __restrict__ beta, float* __restrict__ out,
    const float* __restrict__ pos, const float* __restrict__ tok)
{
    const int r = blockIdx.x;
    const int s = r % S_;
    const int t = threadIdx.x;
    const float* row = in + (size_t)r * D_;
    float x[3];
#pragma unroll
    for (int j = 0; j < 3; ++j) {
        int i = t + j * 256;
        float v = row[i];
        if (pos) v += pos[(size_t)s * D_ + i] + tok[i];
        x[j] = v;
    }
    float sum = x[0] + x[1] + x[2];
    float sq  = x[0] * x[0] + x[1] * x[1] + x[2] * x[2];
    __shared__ float rs[8], rq[8];
#pragma unroll
    for (int o = 16; o > 0; o >>= 1) {
        sum += __shfl_xor_sync(0xffffffffu, sum, o);
        sq  += __shfl_xor_sync(0xffffffffu, sq, o);
    }
    if ((t & 31) == 0) { rs[t >> 5] = sum; rq[t >> 5] = sq; }
    __syncthreads();
    if (t < 32) {
        float s2 = (t < 8) ? rs[t] : 0.f;
        float q2 = (t < 8) ? rq[t] : 0.f;
#pragma unroll
        for (int o = 4; o > 0; o >>= 1) {
            s2 += __shfl_xor_sync(0xffffffffu, s2, o);
            q2 += __shfl_xor_sync(0xffffffffu, q2, o);
        }
        if (t == 0) { rs[0] = s2; rq[0] = q2; }
    }
    __syncthreads();
    const float mean = rs[0] * (1.0f / 768.0f);
    float var = rq[0] * (1.0f / 768.0f) - mean * mean;
    const float rstd = rsqrtf(fmaxf(var, 0.f) + 1e-12f);
#pragma unroll
    for (int j = 0; j < 3; ++j) {
        int i = t + j * 256;
        out[(size_t)r * D_ + i] = (x[j] - mean) * rstd * gamma[i] + beta[i];
    }
}

// ---------------- fused block-sparse attention ----------------
// grid: (NB, H, B), block: 256 threads. Each CTA: 64 queries x (gathered) keys,
// flash-style online softmax. thread -> (row r = tid/4, quarter t4 = tid%4, 16 lanes each).
__global__ __launch_bounds__(256) void attn_kernel(
    const float* __restrict__ q, const float* __restrict__ k,
    const float* __restrict__ v, const float* __restrict__ mask,
    float* __restrict__ ctx)
{
    const int b = blockIdx.z, hh = blockIdx.y, qb = blockIdx.x;
    const int tid = threadIdx.x;
    const int r = tid >> 2, t4 = tid & 3;

    __shared__ float qs[64 * 64];   // Q^T: qs[d][row]
    __shared__ float kps[64 * 64];  // K^T: kps[d][col], later reused as P^T: kps[col][row]
    __shared__ float vs[64 * 64];   // V:   vs[row][d]

    {
        const int row = tid >> 2, dq = tid & 3;
        const float* qp = q + ((size_t)(b * S_ + qb * 64 + row)) * D_ + hh * 64 + dq * 16;
#pragma unroll
        for (int j = 0; j < 4; ++j) {
            float4 tq = *(const float4*)(qp + j * 4);
            int d = dq * 16 + j * 4;
            qs[(d + 0) * 64 + row] = tq.x;
            qs[(d + 1) * 64 + row] = tq.y;
            qs[(d + 2) * 64 + row] = tq.z;
            qs[(d + 3) * 64 + row] = tq.w;
        }
    }

    float acc[16];
#pragma unroll
    for (int i = 0; i < 16; ++i) acc[i] = 0.f;
    float m_run = -1e30f, l_run = 0.f;

    const int cnt = g_gicnt[qb];
    for (int kt = 0; kt < cnt; ++kt) {
        const int kb = g_gi[qb * 64 + kt];
        __syncthreads();  // previous tile fully consumed (also orders the Q load)
        {
            const int row = tid >> 2, dq = tid & 3;
            const float* kp = k + ((size_t)(b * S_ + kb * 64 + row)) * D_ + hh * 64 + dq * 16;
            const float* vp = v + ((size_t)(b * S_ + kb * 64 + row)) * D_ + hh * 64 + dq * 16;
#pragma unroll
            for (int j = 0; j < 4; ++j) {
                int d = dq * 16 + j * 4;
                float4 tk = *(const float4*)(kp + j * 4);
                kps[(d + 0) * 64 + row] = tk.x;
                kps[(d + 1) * 64 + row] = tk.y;
                kps[(d + 2) * 64 + row] = tk.z;
                kps[(d + 3) * 64 + row] = tk.w;
                *(float4*)&vs[row * 64 + d] = *(const float4*)(vp + j * 4);
            }
        }
        __syncthreads();

        // scores for 16 key columns: c = t4*16 + i
        float sc[16];
#pragma unroll
        for (int i = 0; i < 16; ++i) sc[i] = 0.f;
#pragma unroll 8
        for (int kk = 0; kk < 64; ++kk) {
            float qv = qs[kk * 64 + r];
#pragma unroll
            for (int i = 0; i < 16; ++i) sc[i] += qv * kps[kk * 64 + t4 * 16 + i];
        }
        const float* mrow = mask + (size_t)b * S_ + kb * 64 + t4 * 16;
        float tm = -1e30f;
#pragma unroll
        for (int i = 0; i < 16; ++i) {
            sc[i] = sc[i] * 0.125f - 1e9f * (1.0f - mrow[i]);
            tm = fmaxf(tm, sc[i]);
        }
        tm = fmaxf(tm, __shfl_xor_sync(0xffffffffu, tm, 1));
        tm = fmaxf(tm, __shfl_xor_sync(0xffffffffu, tm, 2));
        const float m_new = fmaxf(m_run, tm);
        const float corr = __expf(m_run - m_new);
        float psum = 0.f;
#pragma unroll
        for (int i = 0; i < 16; ++i) {
            sc[i] = __expf(sc[i] - m_new);
            psum += sc[i];
        }
        psum += __shfl_xor_sync(0xffffffffu, psum, 1);
        psum += __shfl_xor_sync(0xffffffffu, psum, 2);
        l_run = l_run * corr + psum;
        m_run = m_new;
#pragma unroll
        for (int i = 0; i < 16; ++i) acc[i] *= corr;

        __syncthreads();  // all threads done reading K before overwriting with P
#pragma unroll
        for (int i = 0; i < 16; ++i) kps[(t4 * 16 + i) * 64 + r] = sc[i];
        __syncthreads();

        // O += P @ V ; thread owns 16 head dims j = t4*16 + i
#pragma unroll 4
        for (int kk = 0; kk < 64; ++kk) {
            float p = kps[kk * 64 + r];
            const float4 v0 = *(const float4*)&vs[kk * 64 + t4 * 16];
            const float4 v1 = *(const float4*)&vs[kk * 64 + t4 * 16 + 4];
            const float4 v2 = *(const float4*)&vs[kk * 64 + t4 * 16 + 8];
            const float4 v3 = *(const float4*)&vs[kk * 64 + t4 * 16 + 12];
            acc[0]  += p * v0.x; acc[1]  += p * v0.y; acc[2]  += p * v0.z; acc[3]  += p * v0.w;
            acc[4]  += p * v1.x; acc[5]  += p * v1.y; acc[6]  += p * v1.z; acc[7]  += p * v1.w;
            acc[8]  += p * v2.x; acc[9]  += p * v2.y; acc[10] += p * v2.z; acc[11] += p * v2.w;
            acc[12] += p * v3.x; acc[13] += p * v3.y; acc[14] += p * v3.z; acc[15] += p * v3.w;
        }
    }

    const float inv = 1.0f / l_run;
    float* op = ctx + ((size_t)(b * S_ + qb * 64 + r)) * D_ + hh * 64 + t4 * 16;
#pragma unroll
    for (int i = 0; i < 16; ++i) op[i] = acc[i] * inv;
}

// ---------------- classifier ----------------
__global__ void cls1_kernel(const float* __restrict__ h, const float* __restrict__ w,
                            const float* __restrict__ bias, float* __restrict__ out)
{
    int gid = blockIdx.x * blockDim.x + threadIdx.x;
    if (gid >= 2 * 512) return;
    int b = gid >> 9, n = gid & 511;
    const float* hrow = h + (size_t)b * S_ * D_;  // token 0
    float s = 0.f;
    for (int k2 = 0; k2 < D_; ++k2) s += hrow[k2] * w[(size_t)k2 * 512 + n];
    s += bias[n];
    out[gid] = fmaxf(s, 0.f);
}

__global__ void cls2_kernel(const float* __restrict__ rin, const float* __restrict__ w,
                            const float* __restrict__ bias, float* __restrict__ out)
{
    int gid = blockIdx.x * blockDim.x + threadIdx.x;
    if (gid >= 2 * TGT_) return;
    int b = gid >> 10, n = gid & 1023;
    float s = 0.f;
    for (int k2 = 0; k2 < 512; ++k2) s += rin[b * 512 + k2] * w[(size_t)k2 * TGT_ + n];
    out[gid] = s + bias[n];
}

// ---------------- host orchestration ----------------
extern "C" void kernel_launch(void* const* d_in, const int* in_sizes, int n_in,
                              void* d_out, int out_size)
{
    const float* x        = (const float*)d_in[0];
    const float* mask     = (const float*)d_in[1];
    const float* proj_w   = (const float*)d_in[2];
    const float* proj_b   = (const float*)d_in[3];
    const float* pos_emb  = (const float*)d_in[4];
    const float* tok_emb  = (const float*)d_in[5];
    const float* emb_g    = (const float*)d_in[6];
    const float* emb_b    = (const float*)d_in[7];
    const float* wq_all   = (const float*)d_in[8];
    const float* bq_all   = (const float*)d_in[9];
    const float* wk_all   = (const float*)d_in[10];
    const float* bk_all   = (const float*)d_in[11];
    const float* wv_all   = (const float*)d_in[12];
    const float* bv_all   = (const float*)d_in[13];
    const float* wo_all   = (const float*)d_in[14];
    const float* bo_all   = (const float*)d_in[15];
    const float* ln1g_all = (const float*)d_in[16];
    const float* ln1b_all = (const float*)d_in[17];
    const float* wi_all   = (const float*)d_in[18];
    const float* bi_all   = (const float*)d_in[19];
    const float* wo2_all  = (const float*)d_in[20];
    const float* bo2_all  = (const float*)d_in[21];
    const float* ln2g_all = (const float*)d_in[22];
    const float* ln2b_all = (const float*)d_in[23];
    const float* cls_w1   = (const float*)d_in[24];
    const float* cls_b1   = (const float*)d_in[25];
    const float* cls_w2   = (const float*)d_in[26];
    const float* cls_b2   = (const float*)d_in[27];
    const int*   rb       = (const int*)d_in[28];
    float* out = (float*)d_out;

    float *ph, *pq, *pk, *pv, *pctx, *ptmp, *pff, *pcls;
    cudaGetSymbolAddress((void**)&ph,   g_h);
    cudaGetSymbolAddress((void**)&pq,   g_q);
    cudaGetSymbolAddress((void**)&pk,   g_k);
    cudaGetSymbolAddress((void**)&pv,   g_v);
    cudaGetSymbolAddress((void**)&pctx, g_ctx);
    cudaGetSymbolAddress((void**)&ptmp, g_tmp);
    cudaGetSymbolAddress((void**)&pff,  g_ff);
    cudaGetSymbolAddress((void**)&pcls, g_cls);

    build_gi_kernel<<<1, 64>>>(rb);

    const dim3 gD(D_ / 128, T_ / 128);   // N=768 output
    const dim3 gF(FF_ / 128, T_ / 128);  // N=3072 output
    const dim3 gA(NB_, H_, B_);

    // embedding: proj + bias, then +pos+tok and LN
    sgemm_kernel<false, false><<<gD, 256>>>(x, proj_w, proj_b, nullptr, ptmp, T_, D_, IN_);
    ln_kernel<<<T_, 256>>>(ptmp, emb_g, emb_b, ph, pos_emb, tok_emb);

    for (int l = 0; l < L_; ++l) {
        const float* wq = wq_all + (size_t)l * D_ * D_;
        const float* wk = wk_all + (size_t)l * D_ * D_;
        const float* wv = wv_all + (size_t)l * D_ * D_;
        const float* wo = wo_all + (size_t)l * D_ * D_;
        const float* bq = bq_all + (size_t)l * D_;
        const float* bk = bk_all + (size_t)l * D_;
        const float* bv = bv_all + (size_t)l * D_;
        const float* bo = bo_all + (size_t)l * D_;
        const float* wi = wi_all + (size_t)l * D_ * FF_;
        const float* bi = bi_all + (size_t)l * FF_;
        const float* wo2 = wo2_all + (size_t)l * FF_ * D_;
        const float* bo2 = bo2_all + (size_t)l * D_;

        sgemm_kernel<false, false><<<gD, 256>>>(ph, wq, bq, nullptr, pq, T_, D_, D_);
        sgemm_kernel<false, false><<<gD, 256>>>(ph, wk, bk, nullptr, pk, T_, D_, D_);
        sgemm_kernel<false, false><<<gD, 256>>>(ph, wv, bv, nullptr, pv, T_, D_, D_);

        attn_kernel<<<gA, 256>>>(pq, pk, pv, mask, pctx);

        sgemm_kernel<false, true><<<gD, 256>>>(pctx, wo, bo, ph, ptmp, T_, D_, D_);
        ln_kernel<<<T_, 256>>>(ptmp, ln1g_all + (size_t)l * D_, ln1b_all + (size_t)l * D_,
                               ph, nullptr, nullptr);

        sgemm_kernel<true, false><<<gF, 256>>>(ph, wi, bi, nullptr, pff, T_, FF_, D_);
        sgemm_kernel<false, true><<<gD, 256>>>(pff, wo2, bo2, ph, ptmp, T_, D_, FF_);
        ln_kernel<<<T_, 256>>>(ptmp, ln2g_all + (size_t)l * D_, ln2b_all + (size_t)l * D_,
                               ph, nullptr, nullptr);
    }

    cls1_kernel<<<4, 256>>>(ph, cls_w1, cls_b1, pcls);
    cls2_kernel<<<8, 256>>>(pcls, cls_w2, cls_b2, out);
}

// round 2
// speedup vs baseline: 2.0198x; 2.0198x over previous
#include <cuda_runtime.h>
#include <cuda_bf16.h>
#include <math.h>
#include <stdint.h>

#define B_    2
#define S_    4096
#define T_    8192
#define IN_   1280
#define D_    768
#define H_    12
#define HD_   64
#define BS_   64
#define NB_   64
#define FF_   3072
#define L_    12
#define TGT_  1024

// -------- weight plane arena offsets --------
#define WN_PROJ (IN_*D_)
#define WN_DD   (L_*D_*D_)
#define WN_DF   (L_*D_*FF_)
#define OFF_PROJ 0
#define OFF_WQ  (OFF_PROJ + WN_PROJ)
#define OFF_WK  (OFF_WQ + WN_DD)
#define OFF_WV  (OFF_WK + WN_DD)
#define OFF_WO  (OFF_WV + WN_DD)
#define OFF_WI  (OFF_WO + WN_DD)
#define OFF_WO2 (OFF_WI + WN_DF)
#define WTOT    (OFF_WO2 + WN_DF)

// ---------------- scratch ----------------
__device__ float g_h[T_ * D_];
__device__ float g_q[T_ * D_];
__device__ float g_k[T_ * D_];
__device__ float g_v[T_ * D_];
__device__ float g_tmp[T_ * D_];
__device__ float g_cls[2 * 512];
__device__ int   g_gi[NB_ * 8];

__device__ __nv_bfloat16 g_whi[WTOT];
__device__ __nv_bfloat16 g_wlo[WTOT];
__device__ __nv_bfloat16 g_xhi[T_ * IN_];
__device__ __nv_bfloat16 g_xlo[T_ * IN_];
__device__ __nv_bfloat16 g_hhi[T_ * D_];
__device__ __nv_bfloat16 g_hlo[T_ * D_];
__device__ __nv_bfloat16 g_chi[T_ * D_];
__device__ __nv_bfloat16 g_clo[T_ * D_];
__device__ __nv_bfloat16 g_fhi[T_ * FF_];
__device__ __nv_bfloat16 g_flo[T_ * FF_];
__device__ float g_part[B_ * H_ * 2 * 8 * 64 * 66];

// ---------------- PTX helpers ----------------
__device__ __forceinline__ void ldsm4(uint32_t& r0, uint32_t& r1, uint32_t& r2, uint32_t& r3, const void* p) {
    uint32_t a = (uint32_t)__cvta_generic_to_shared(p);
    asm volatile("ldmatrix.sync.aligned.m8n8.x4.shared.b16 {%0,%1,%2,%3}, [%4];"
                 : "=r"(r0), "=r"(r1), "=r"(r2), "=r"(r3) : "r"(a));
}
__device__ __forceinline__ void ldsm4t(uint32_t& r0, uint32_t& r1, uint32_t& r2, uint32_t& r3, const void* p) {
    uint32_t a = (uint32_t)__cvta_generic_to_shared(p);
    asm volatile("ldmatrix.sync.aligned.m8n8.x4.trans.shared.b16 {%0,%1,%2,%3}, [%4];"
                 : "=r"(r0), "=r"(r1), "=r"(r2), "=r"(r3) : "r"(a));
}
__device__ __forceinline__ void mma16816(float* d, const uint32_t* a, uint32_t b0, uint32_t b1) {
    asm volatile("mma.sync.aligned.m16n8k16.row.col.f32.bf16.bf16.f32 "
                 "{%0,%1,%2,%3}, {%4,%5,%6,%7}, {%8,%9}, {%0,%1,%2,%3};"
                 : "+f"(d[0]), "+f"(d[1]), "+f"(d[2]), "+f"(d[3])
                 : "r"(a[0]), "r"(a[1]), "r"(a[2]), "r"(a[3]), "r"(b0), "r"(b1));
}
__device__ __forceinline__ void cpa16(void* dst, const void* src) {
    uint32_t d = (uint32_t)__cvta_generic_to_shared(dst);
    asm volatile("cp.async.cg.shared.global [%0], [%1], 16;" :: "r"(d), "l"(src));
}

// ---------------- split fp32 -> bf16 hi/lo ----------------
__global__ void split_kernel(const float* __restrict__ src,
                             __nv_bfloat16* __restrict__ hi,
                             __nv_bfloat16* __restrict__ lo, int n)
{
    int i = blockIdx.x * blockDim.x + threadIdx.x;
    if (i >= n) return;
    float v = src[i];
    __nv_bfloat16 h = __float2bfloat16(v);
    hi[i] = h;
    lo[i] = __float2bfloat16(v - __bfloat162float(h));
}

// ---------------- gather-list (mid blocks only) ----------------
__global__ void build_gi_kernel(const int* __restrict__ rb) {
    int n = threadIdx.x;
    if (n < 1 || n >= NB_ - 1) return;
    int* p = g_gi + n * 8;
    p[0] = 0; p[1] = n - 1; p[2] = n; p[3] = n + 1; p[4] = NB_ - 1;
    p[5] = rb[n * 3 + 0]; p[6] = rb[n * 3 + 1]; p[7] = rb[n * 3 + 2];
}

// ---------------- bf16x3 tensor-core GEMM ----------------
// C[M,N] = A[M,K] @ B[K,N] + bias  (A,B given as bf16 hi/lo planes)
// CTA 128x128, 256 thr = 8 warps (4x2 of 32x64 warp tiles), BK=16, cp.async double buffer.
template<bool GELU, bool RES, bool SPLITOUT, bool WRITEF32>
__global__ __launch_bounds__(256) void bgemm_kernel(
    const __nv_bfloat16* __restrict__ Ahi, const __nv_bfloat16* __restrict__ Alo,
    const __nv_bfloat16* __restrict__ Bhi, const __nv_bfloat16* __restrict__ Blo,
    const float* __restrict__ bias, const float* __restrict__ res,
    float* __restrict__ C, __nv_bfloat16* __restrict__ Chi, __nv_bfloat16* __restrict__ Clo,
    int M, int N, int K)
{
    __shared__ __nv_bfloat16 sA[2][2][128][24];  // [stage][plane][row][k(16)+pad]
    __shared__ __nv_bfloat16 sB[2][2][16][136];  // [stage][plane][k][n(128)+pad]

    const int tid = threadIdx.x;
    const int warp = tid >> 5, lane = tid & 31;
    const int wr = warp >> 1, wc = warp & 1;
    const int m0 = blockIdx.y * 128, n0 = blockIdx.x * 128;
    const int nk = K >> 4;

    float acc[2][8][4];
#pragma unroll
    for (int mi = 0; mi < 2; ++mi)
#pragma unroll
        for (int ni = 0; ni < 8; ++ni)
#pragma unroll
            for (int r = 0; r < 4; ++r) acc[mi][ni][r] = 0.f;

    // copy assignments
    const int a_pl = tid >> 8;  // always 0 for first chunk; second chunk uses +256
    auto load_stage = [&](int st, int kt) {
        const int k0 = kt << 4;
#pragma unroll
        for (int c2 = 0; c2 < 2; ++c2) {
            int c = tid + c2 * 256;
            int pl = c >> 8, row = (c >> 1) & 127, kh = c & 1;
            const __nv_bfloat16* src = (pl ? Alo : Ahi) + (size_t)(m0 + row) * K + k0 + kh * 8;
            cpa16(&sA[st][pl][row][kh * 8], src);
        }
#pragma unroll
        for (int c2 = 0; c2 < 2; ++c2) {
            int c = tid + c2 * 256;
            int pl = c >> 8, kr = (c >> 4) & 15, nc = c & 15;
            const __nv_bfloat16* src = (pl ? Blo : Bhi) + (size_t)(k0 + kr) * N + n0 + nc * 8;
            cpa16(&sB[st][pl][kr][nc * 8], src);
        }
    };
    (void)a_pl;

    load_stage(0, 0);
    asm volatile("cp.async.commit_group;");

    const int arow = lane & 15;
    const int acol = (lane >> 4) * 8;
    const int krow = lane & 15;

    for (int kt = 0; kt < nk; ++kt) {
        const int st = kt & 1;
        if (kt + 1 < nk) {
            load_stage(st ^ 1, kt + 1);
            asm volatile("cp.async.commit_group;");
            asm volatile("cp.async.wait_group 1;");
        } else {
            asm volatile("cp.async.wait_group 0;");
        }
        __syncthreads();

        uint32_t ah[2][4], al[2][4];
#pragma unroll
        for (int mi = 0; mi < 2; ++mi) {
            ldsm4(ah[mi][0], ah[mi][1], ah[mi][2], ah[mi][3], &sA[st][0][wr * 32 + mi * 16 + arow][acol]);
            ldsm4(al[mi][0], al[mi][1], al[mi][2], al[mi][3], &sA[st][1][wr * 32 + mi * 16 + arow][acol]);
        }
#pragma unroll
        for (int np = 0; np < 4; ++np) {
            const int ncol = wc * 64 + np * 16 + ((lane & 16) ? 8 : 0);
            uint32_t bh[4], bl[4];
            ldsm4t(bh[0], bh[1], bh[2], bh[3], &sB[st][0][krow][ncol]);
            ldsm4t(bl[0], bl[1], bl[2], bl[3], &sB[st][1][krow][ncol]);
#pragma unroll
            for (int j = 0; j < 2; ++j) {
                const int ni = np * 2 + j;
#pragma unroll
                for (int mi = 0; mi < 2; ++mi) {
                    mma16816(acc[mi][ni], ah[mi], bh[2 * j], bh[2 * j + 1]);
                    mma16816(acc[mi][ni], ah[mi], bl[2 * j], bl[2 * j + 1]);
                    mma16816(acc[mi][ni], al[mi], bh[2 * j], bh[2 * j + 1]);
                }
            }
        }
        __syncthreads();
    }

    // epilogue
#pragma unroll
    for (int mi = 0; mi < 2; ++mi) {
        const int rbase = m0 + wr * 32 + mi * 16 + (lane >> 2);
#pragma unroll
        for (int ni = 0; ni < 8; ++ni) {
            const int cbase = n0 + wc * 64 + ni * 8 + (lane & 3) * 2;
            const float b0 = bias[cbase], b1 = bias[cbase + 1];
#pragma unroll
            for (int hrow = 0; hrow < 2; ++hrow) {
                const int row = rbase + hrow * 8;
                float v0 = acc[mi][ni][hrow * 2 + 0] + b0;
                float v1 = acc[mi][ni][hrow * 2 + 1] + b1;
                if (RES) {
                    v0 += res[(size_t)row * N + cbase];
                    v1 += res[(size_t)row * N + cbase + 1];
                }
                if (GELU) {
                    float u = v0;
                    v0 = 0.5f * u * (1.0f + tanhf(0.7978845608028654f * (u + 0.044715f * u * u * u)));
                    u = v1;
                    v1 = 0.5f * u * (1.0f + tanhf(0.7978845608028654f * (u + 0.044715f * u * u * u)));
                }
                const size_t idx = (size_t)row * N + cbase;
                if (WRITEF32) {
                    C[idx] = v0; C[idx + 1] = v1;
                }
                if (SPLITOUT) {
                    __nv_bfloat16 h0 = __float2bfloat16(v0);
                    __nv_bfloat16 h1 = __float2bfloat16(v1);
                    Chi[idx] = h0; Chi[idx + 1] = h1;
                    Clo[idx]     = __float2bfloat16(v0 - __bfloat162float(h0));
                    Clo[idx + 1] = __float2bfloat16(v1 - __bfloat162float(h1));
                }
            }
        }
    }
}

// ---------------- LayerNorm (fused bf16 split output) ----------------
__global__ __launch_bounds__(256) void ln_kernel(
    const float* __restrict__ in, const float* __restrict__ gamma,
    const float* __restrict__ beta, float* __restrict__ out,
    __nv_bfloat16* __restrict__ ohi, __nv_bfloat16* __restrict__ olo,
    const float* __restrict__ pos, const float* __restrict__ tok)
{
    const int r = blockIdx.x;
    const int s = r % S_;
    const int t = threadIdx.x;
    const float* row = in + (size_t)r * D_;
    float x[3];
#pragma unroll
    for (int j = 0; j < 3; ++j) {
        int i = t + j * 256;
        float v = row[i];
        if (pos) v += pos[(size_t)s * D_ + i] + tok[i];
        x[j] = v;
    }
    float sum = x[0] + x[1] + x[2];
    float sq  = x[0] * x[0] + x[1] * x[1] + x[2] * x[2];
    __shared__ float rs[8], rq[8];
#pragma unroll
    for (int o = 16; o > 0; o >>= 1) {
        sum += __shfl_xor_sync(0xffffffffu, sum, o);
        sq  += __shfl_xor_sync(0xffffffffu, sq, o);
    }
    if ((t & 31) == 0) { rs[t >> 5] = sum; rq[t >> 5] = sq; }
    __syncthreads();
    if (t < 32) {
        float s2 = (t < 8) ? rs[t] : 0.f;
        float q2 = (t < 8) ? rq[t] : 0.f;
#pragma unroll
        for (int o = 4; o > 0; o >>= 1) {
            s2 += __shfl_xor_sync(0xffffffffu, s2, o);
            q2 += __shfl_xor_sync(0xffffffffu, q2, o);
        }
        if (t == 0) { rs[0] = s2; rq[0] = q2; }
    }
    __syncthreads();
    const float mean = rs[0] * (1.0f / 768.0f);
    float var = rq[0] * (1.0f / 768.0f) - mean * mean;
    const float rstd = rsqrtf(fmaxf(var, 0.f) + 1e-12f);
#pragma unroll
    for (int j = 0; j < 3; ++j) {
        int i = t + j * 256;
        float y = (x[j] - mean) * rstd * gamma[i] + beta[i];
        size_t idx = (size_t)r * D_ + i;
        out[idx] = y;
        __nv_bfloat16 h = __float2bfloat16(y);
        ohi[idx] = h;
        olo[idx] = __float2bfloat16(y - __bfloat162float(h));
    }
}

// ---------------- fused block-sparse attention ----------------
// grid (78, H, B): idx<62 -> mid block qb=idx+1 (8 gathered tiles, full softmax).
// idx>=62 -> edge block slices: 8 CTAs per edge block, 8 consecutive key tiles each,
// writing partial (acc,m,l) to g_part for the merge kernel.
__global__ __launch_bounds__(256) void attn_kernel(
    const float* __restrict__ q, const float* __restrict__ k,
    const float* __restrict__ v, const float* __restrict__ mask)
{
    const int b = blockIdx.z, hh = blockIdx.y, ib = blockIdx.x;
    const int tid = threadIdx.x;
    const int r = tid >> 2, t4 = tid & 3;

    int qb, t0 = 0, e = 0, slice = 0;
    bool edge;
    if (ib < 62) { qb = ib + 1; edge = false; }
    else {
        edge = true;
        int xx = ib - 62;
        e = xx >> 3; slice = xx & 7;
        qb = e ? (NB_ - 1) : 0;
        t0 = slice * 8;
    }

    __shared__ float qs[64 * 64];   // Q^T
    __shared__ float kps[64 * 64];  // K^T then P^T
    __shared__ float vs[64 * 64];   // V

    {
        const int row = tid >> 2, dq = tid & 3;
        const float* qp = q + ((size_t)(b * S_ + qb * 64 + row)) * D_ + hh * 64 + dq * 16;
#pragma unroll
        for (int j = 0; j < 4; ++j) {
            float4 tq = *(const float4*)(qp + j * 4);
            int d = dq * 16 + j * 4;
            qs[(d + 0) * 64 + row] = tq.x;
            qs[(d + 1) * 64 + row] = tq.y;
            qs[(d + 2) * 64 + row] = tq.z;
            qs[(d + 3) * 64 + row] = tq.w;
        }
    }

    float acc[16];
#pragma unroll
    for (int i = 0; i < 16; ++i) acc[i] = 0.f;
    float m_run = -1e30f, l_run = 0.f;

    for (int kt = 0; kt < 8; ++kt) {
        const int kb = edge ? (t0 + kt) : g_gi[qb * 8 + kt];
        __syncthreads();
        {
            const int row = tid >> 2, dq = tid & 3;
            const float* kp = k + ((size_t)(b * S_ + kb * 64 + row)) * D_ + hh * 64 + dq * 16;
            const float* vp = v + ((size_t)(b * S_ + kb * 64 + row)) * D_ + hh * 64 + dq * 16;
#pragma unroll
            for (int j = 0; j < 4; ++j) {
                int d = dq * 16 + j * 4;
                float4 tk = *(const float4*)(kp + j * 4);
                kps[(d + 0) * 64 + row] = tk.x;
                kps[(d + 1) * 64 + row] = tk.y;
                kps[(d + 2) * 64 + row] = tk.z;
                kps[(d + 3) * 64 + row] = tk.w;
                *(float4*)&vs[row * 64 + d] = *(const float4*)(vp + j * 4);
            }
        }
        __syncthreads();

        float sc[16];
#pragma unroll
        for (int i = 0; i < 16; ++i) sc[i] = 0.f;
#pragma unroll 8
        for (int kk = 0; kk < 64; ++kk) {
            float qv = qs[kk * 64 + r];
#pragma unroll
            for (int i = 0; i < 16; ++i) sc[i] += qv * kps[kk * 64 + t4 * 16 + i];
        }
        const float* mrow = mask + (size_t)b * S_ + kb * 64 + t4 * 16;
        float tm = -1e30f;
#pragma unroll
        for (int i = 0; i < 16; ++i) {
            sc[i] = sc[i] * 0.125f - 1e9f * (1.0f - mrow[i]);
            tm = fmaxf(tm, sc[i]);
        }
        tm = fmaxf(tm, __shfl_xor_sync(0xffffffffu, tm, 1));
        tm = fmaxf(tm, __shfl_xor_sync(0xffffffffu, tm, 2));
        const float m_new = fmaxf(m_run, tm);
        const float corr = __expf(m_run - m_new);
        float psum = 0.f;
#pragma unroll
        for (int i = 0; i < 16; ++i) {
            sc[i] = __expf(sc[i] - m_new);
            psum += sc[i];
        }
        psum += __shfl_xor_sync(0xffffffffu, psum, 1);
        psum += __shfl_xor_sync(0xffffffffu, psum, 2);
        l_run = l_run * corr + psum;
        m_run = m_new;
#pragma unroll
        for (int i = 0; i < 16; ++i) acc[i] *= corr;

        __syncthreads();
#pragma unroll
        for (int i = 0; i < 16; ++i) kps[(t4 * 16 + i) * 64 + r] = sc[i];
        __syncthreads();

#pragma unroll 4
        for (int kk = 0; kk < 64; ++kk) {
            float p = kps[kk * 64 + r];
            const float4 v0 = *(const float4*)&vs[kk * 64 + t4 * 16];
            const float4 v1 = *(const float4*)&vs[kk * 64 + t4 * 16 + 4];
            const float4 v2 = *(const float4*)&vs[kk * 64 + t4 * 16 + 8];
            const float4 v3 = *(const float4*)&vs[kk * 64 + t4 * 16 + 12];
            acc[0]  += p * v0.x; acc[1]  += p * v0.y; acc[2]  += p * v0.z; acc[3]  += p * v0.w;
            acc[4]  += p * v1.x; acc[5]  += p * v1.y; acc[6]  += p * v1.z; acc[7]  += p * v1.w;
            acc[8]  += p * v2.x; acc[9]  += p * v2.y; acc[10] += p * v2.z; acc[11] += p * v2.w;
            acc[12] += p * v3.x; acc[13] += p * v3.y; acc[14] += p * v3.z; acc[15] += p * v3.w;
        }
    }

    if (!edge) {
        const float inv = 1.0f / l_run;
        const size_t idx = ((size_t)(b * S_ + qb * 64 + r)) * D_ + hh * 64 + t4 * 16;
#pragma unroll
        for (int i = 0; i < 16; ++i) {
            float vv = acc[i] * inv;
            __nv_bfloat16 h = __float2bfloat16(vv);
            g_chi[idx + i] = h;
            g_clo[idx + i] = __float2bfloat16(vv - __bfloat162float(h));
        }
    } else {
        float* pp = g_part + ((size_t)((((b * H_ + hh) * 2 + e) * 8 + slice) * 64 + r)) * 66;
#pragma unroll
        for (int i = 0; i < 16; ++i) pp[t4 * 16 + i] = acc[i];
        if (t4 == 0) { pp[64] = m_run; pp[65] = l_run; }
    }
}

// merge the 8 partial slices for each edge block row
__global__ __launch_bounds__(256) void merge_kernel() {
    const int e = blockIdx.x, hh = blockIdx.y, b = blockIdx.z;
    const int tid = threadIdx.x;
    const int r = tid >> 2, t4 = tid & 3;
    const size_t base = ((size_t)(((b * H_ + hh) * 2 + e) * 8)) * 64 * 66;

    float M = -1e30f;
#pragma unroll
    for (int s = 0; s < 8; ++s) M = fmaxf(M, g_part[base + ((size_t)s * 64 + r) * 66 + 64]);
    float L = 0.f;
    float acc[16];
#pragma unroll
    for (int i = 0; i < 16; ++i) acc[i] = 0.f;
#pragma unroll
    for (int s = 0; s < 8; ++s) {
        const float* pp = g_part + base + ((size_t)s * 64 + r) * 66;
        const float w = __expf(pp[64] - M);
        L += pp[65] * w;
#pragma unroll
        for (int i = 0; i < 16; ++i) acc[i] += pp[t4 * 16 + i] * w;
    }
    const float inv = 1.0f / L;
    const int qb = e ? (NB_ - 1) : 0;
    const size_t idx = ((size_t)(b * S_ + qb * 64 + r)) * D_ + hh * 64 + t4 * 16;
#pragma unroll
    for (int i = 0; i < 16; ++i) {
        float vv = acc[i] * inv;
        __nv_bfloat16 h = __float2bfloat16(vv);
        g_chi[idx + i] = h;
        g_clo[idx + i] = __float2bfloat16(vv - __bfloat162float(h));
    }
}

// ---------------- classifier ----------------
__global__ void cls1_kernel(const float* __restrict__ h, const float* __restrict__ w,
                            const float* __restrict__ bias, float* __restrict__ out)
{
    int gid = blockIdx.x * blockDim.x + threadIdx.x;
    if (gid >= 2 * 512) return;
    int b = gid >> 9, n = gid & 511;
    const float* hrow = h + (size_t)b * S_ * D_;
    float s = 0.f;
    for (int k2 = 0; k2 < D_; ++k2) s += hrow[k2] * w[(size_t)k2 * 512 + n];
    s += bias[n];
    out[gid] = fmaxf(s, 0.f);
}

__global__ void cls2_kernel(const float* __restrict__ rin, const float* __restrict__ w,
                            const float* __restrict__ bias, float* __restrict__ out)
{
    int gid = blockIdx.x * blockDim.x + threadIdx.x;
    if (gid >= 2 * TGT_) return;
    int b = gid >> 10, n = gid & 1023;
    float s = 0.f;
    for (int k2 = 0; k2 < 512; ++k2) s += rin[b * 512 + k2] * w[(size_t)k2 * TGT_ + n];
    out[gid] = s + bias[n];
}

// ---------------- host orchestration ----------------
extern "C" void kernel_launch(void* const* d_in, const int* in_sizes, int n_in,
                              void* d_out, int out_size)
{
    const float* x        = (const float*)d_in[0];
    const float* mask     = (const float*)d_in[1];
    const float* proj_w   = (const float*)d_in[2];
    const float* proj_b   = (const float*)d_in[3];
    const float* pos_emb  = (const float*)d_in[4];
    const float* tok_emb  = (const float*)d_in[5];
    const float* emb_g    = (const float*)d_in[6];
    const float* emb_b    = (const float*)d_in[7];
    const float* bq_all   = (const float*)d_in[9];
    const float* bk_all   = (const float*)d_in[11];
    const float* bv_all   = (const float*)d_in[13];
    const float* bo_all   = (const float*)d_in[15];
    const float* ln1g_all = (const float*)d_in[16];
    const float* ln1b_all = (const float*)d_in[17];
    const float* bi_all   = (const float*)d_in[19];
    const float* bo2_all  = (const float*)d_in[21];
    const float* ln2g_all = (const float*)d_in[22];
    const float* ln2b_all = (const float*)d_in[23];
    const float* cls_w1   = (const float*)d_in[24];
    const float* cls_b1   = (const float*)d_in[25];
    const float* cls_w2   = (const float*)d_in[26];
    const float* cls_b2   = (const float*)d_in[27];
    const int*   rb       = (const int*)d_in[28];
    float* out = (float*)d_out;

    float *ph, *pq, *pk, *pv, *ptmp, *pcls;
    __nv_bfloat16 *pwhi, *pwlo, *pxhi, *pxlo, *phhi, *phlo, *pchi, *pclo, *pfhi, *pflo;
    cudaGetSymbolAddress((void**)&ph,   g_h);
    cudaGetSymbolAddress((void**)&pq,   g_q);
    cudaGetSymbolAddress((void**)&pk,   g_k);
    cudaGetSymbolAddress((void**)&pv,   g_v);
    cudaGetSymbolAddress((void**)&ptmp, g_tmp);
    cudaGetSymbolAddress((void**)&pcls, g_cls);
    cudaGetSymbolAddress((void**)&pwhi, g_whi);
    cudaGetSymbolAddress((void**)&pwlo, g_wlo);
    cudaGetSymbolAddress((void**)&pxhi, g_xhi);
    cudaGetSymbolAddress((void**)&pxlo, g_xlo);
    cudaGetSymbolAddress((void**)&phhi, g_hhi);
    cudaGetSymbolAddress((void**)&phlo, g_hlo);
    cudaGetSymbolAddress((void**)&pchi, g_chi);
    cudaGetSymbolAddress((void**)&pclo, g_clo);
    cudaGetSymbolAddress((void**)&pfhi, g_fhi);
    cudaGetSymbolAddress((void**)&pflo, g_flo);

    // split all weights + input into bf16 hi/lo planes
    auto split = [&](const float* src, __nv_bfloat16* hi, __nv_bfloat16* lo, int n) {
        split_kernel<<<(n + 255) / 256, 256>>>(src, hi, lo, n);
    };
    split((const float*)d_in[2],  pwhi + OFF_PROJ, pwlo + OFF_PROJ, WN_PROJ);
    split((const float*)d_in[8],  pwhi + OFF_WQ,   pwlo + OFF_WQ,   WN_DD);
    split((const float*)d_in[10], pwhi + OFF_WK,   pwlo + OFF_WK,   WN_DD);
    split((const float*)d_in[12], pwhi + OFF_WV,   pwlo + OFF_WV,   WN_DD);
    split((const float*)d_in[14], pwhi + OFF_WO,   pwlo + OFF_WO,   WN_DD);
    split((const float*)d_in[18], pwhi + OFF_WI,   pwlo + OFF_WI,   WN_DF);
    split((const float*)d_in[20], pwhi + OFF_WO2,  pwlo + OFF_WO2,  WN_DF);
    split(x, pxhi, pxlo, T_ * IN_);
    build_gi_kernel<<<1, 64>>>(rb);
    (void)proj_w;

    const dim3 gD(D_ / 128, T_ / 128);
    const dim3 gF(FF_ / 128, T_ / 128);
    const dim3 gA(78, H_, B_);
    const dim3 gM(2, H_, B_);

    // embedding
    bgemm_kernel<false, false, false, true><<<gD, 256>>>(
        pxhi, pxlo, pwhi + OFF_PROJ, pwlo + OFF_PROJ, proj_b, nullptr,
        ptmp, nullptr, nullptr, T_, D_, IN_);
    ln_kernel<<<T_, 256>>>(ptmp, emb_g, emb_b, ph, phhi, phlo, pos_emb, tok_emb);

    for (int l = 0; l < L_; ++l) {
        const size_t odd = (size_t)l * D_ * D_;
        const size_t odf = (size_t)l * D_ * FF_;

        bgemm_kernel<false, false, false, true><<<gD, 256>>>(
            phhi, phlo, pwhi + OFF_WQ + odd, pwlo + OFF_WQ + odd, bq_all + (size_t)l * D_,
            nullptr, pq, nullptr, nullptr, T_, D_, D_);
        bgemm_kernel<false, false, false, true><<<gD, 256>>>(
            phhi, phlo, pwhi + OFF_WK + odd, pwlo + OFF_WK + odd, bk_all + (size_t)l * D_,
            nullptr, pk, nullptr, nullptr, T_, D_, D_);
        bgemm_kernel<false, false, false, true><<<gD, 256>>>(
            phhi, phlo, pwhi + OFF_WV + odd, pwlo + OFF_WV + odd, bv_all + (size_t)l * D_,
            nullptr, pv, nullptr, nullptr, T_, D_, D_);

        attn_kernel<<<gA, 256>>>(pq, pk, pv, mask);
        merge_kernel<<<gM, 256>>>();

        bgemm_kernel<false, true, false, true><<<gD, 256>>>(
            pchi, pclo, pwhi + OFF_WO + odd, pwlo + OFF_WO + odd, bo_all + (size_t)l * D_,
            ph, ptmp, nullptr, nullptr, T_, D_, D_);
        ln_kernel<<<T_, 256>>>(ptmp, ln1g_all + (size_t)l * D_, ln1b_all + (size_t)l * D_,
                               ph, phhi, phlo, nullptr, nullptr);

        bgemm_kernel<true, false, true, false><<<gF, 256>>>(
            phhi, phlo, pwhi + OFF_WI + odf, pwlo + OFF_WI + odf, bi_all + (size_t)l * FF_,
            nullptr, nullptr, pfhi, pflo, T_, FF_, D_);
        bgemm_kernel<false, true, false, true><<<gD, 256>>>(
            pfhi, pflo, pwhi + OFF_WO2 + odf, pwlo + OFF_WO2 + odf, bo2_all + (size_t)l * D_,
            ph, ptmp, nullptr, nullptr, T_, D_, FF_);
        ln_kernel<<<T_, 256>>>(ptmp, ln2g_all + (size_t)l * D_, ln2b_all + (size_t)l * D_,
                               ph, phhi, phlo, nullptr, nullptr);
    }

    cls1_kernel<<<4, 256>>>(ph, cls_w1, cls_b1, pcls);
    cls2_kernel<<<8, 256>>>(pcls, cls_w2, cls_b2, out);
}

// round 3
// speedup vs baseline: 2.0279x; 1.0040x over previous
#include <cuda_runtime.h>
#include <cuda_bf16.h>
#include <math.h>
#include <stdint.h>

#define B_    2
#define S_    4096
#define T_    8192
#define IN_   1280
#define D_    768
#define H_    12
#define HD_   64
#define BS_   64
#define NB_   64
#define FF_   3072
#define L_    12
#define TGT_  1024

// -------- weight plane arena offsets --------
#define WN_PROJ (IN_*D_)
#define WN_DD   (L_*D_*D_)
#define WN_DF   (L_*D_*FF_)
#define OFF_PROJ 0
#define OFF_WQ  (OFF_PROJ + WN_PROJ)
#define OFF_WK  (OFF_WQ + WN_DD)
#define OFF_WV  (OFF_WK + WN_DD)
#define OFF_WO  (OFF_WV + WN_DD)
#define OFF_WI  (OFF_WO + WN_DD)
#define OFF_WO2 (OFF_WI + WN_DF)
#define WTOT    (OFF_WO2 + WN_DF)

// ---------------- scratch ----------------
__device__ float g_h[T_ * D_];
__device__ float g_q[T_ * D_];
__device__ float g_k[T_ * D_];
__device__ float g_v[T_ * D_];
__device__ float g_tmp[T_ * D_];
__device__ float g_cls[2 * 512];
__device__ int   g_gi[NB_ * 8];

__device__ __nv_bfloat16 g_whi[WTOT];
__device__ __nv_bfloat16 g_wlo[WTOT];
__device__ __nv_bfloat16 g_xhi[T_ * IN_];
__device__ __nv_bfloat16 g_xlo[T_ * IN_];
__device__ __nv_bfloat16 g_hhi[T_ * D_];
__device__ __nv_bfloat16 g_hlo[T_ * D_];
__device__ __nv_bfloat16 g_chi[T_ * D_];
__device__ __nv_bfloat16 g_clo[T_ * D_];
__device__ __nv_bfloat16 g_fhi[T_ * FF_];
__device__ __nv_bfloat16 g_flo[T_ * FF_];
__device__ float g_part[B_ * H_ * 2 * 8 * 64 * 66];

// ---------------- PTX helpers ----------------
__device__ __forceinline__ void ldsm4(uint32_t& r0, uint32_t& r1, uint32_t& r2, uint32_t& r3, const void* p) {
    uint32_t a = (uint32_t)__cvta_generic_to_shared(p);
    asm volatile("ldmatrix.sync.aligned.m8n8.x4.shared.b16 {%0,%1,%2,%3}, [%4];"
                 : "=r"(r0), "=r"(r1), "=r"(r2), "=r"(r3) : "r"(a));
}
__device__ __forceinline__ void ldsm4t(uint32_t& r0, uint32_t& r1, uint32_t& r2, uint32_t& r3, const void* p) {
    uint32_t a = (uint32_t)__cvta_generic_to_shared(p);
    asm volatile("ldmatrix.sync.aligned.m8n8.x4.trans.shared.b16 {%0,%1,%2,%3}, [%4];"
                 : "=r"(r0), "=r"(r1), "=r"(r2), "=r"(r3) : "r"(a));
}
__device__ __forceinline__ void mma16816(float* d, const uint32_t* a, uint32_t b0, uint32_t b1) {
    asm volatile("mma.sync.aligned.m16n8k16.row.col.f32.bf16.bf16.f32 "
                 "{%0,%1,%2,%3}, {%4,%5,%6,%7}, {%8,%9}, {%0,%1,%2,%3};"
                 : "+f"(d[0]), "+f"(d[1]), "+f"(d[2]), "+f"(d[3])
                 : "r"(a[0]), "r"(a[1]), "r"(a[2]), "r"(a[3]), "r"(b0), "r"(b1));
}
__device__ __forceinline__ void cpa16(void* dst, const void* src) {
    uint32_t d = (uint32_t)__cvta_generic_to_shared(dst);
    asm volatile("cp.async.cg.shared.global [%0], [%1], 16;" :: "r"(d), "l"(src));
}

// ---------------- split fp32 -> bf16 hi/lo ----------------
__global__ void split_kernel(const float* __restrict__ src,
                             __nv_bfloat16* __restrict__ hi,
                             __nv_bfloat16* __restrict__ lo, int n)
{
    int i = blockIdx.x * blockDim.x + threadIdx.x;
    if (i >= n) return;
    float v = src[i];
    __nv_bfloat16 h = __float2bfloat16(v);
    hi[i] = h;
    lo[i] = __float2bfloat16(v - __bfloat162float(h));
}

// ---------------- gather-list (mid blocks only) ----------------
__global__ void build_gi_kernel(const int* __restrict__ rb) {
    int n = threadIdx.x;
    if (n < 1 || n >= NB_ - 1) return;
    int* p = g_gi + n * 8;
    p[0] = 0; p[1] = n - 1; p[2] = n; p[3] = n + 1; p[4] = NB_ - 1;
    p[5] = rb[n * 3 + 0]; p[6] = rb[n * 3 + 1]; p[7] = rb[n * 3 + 2];
}

// ---------------- bf16x3 tensor-core GEMM ----------------
// C[M,N] = A[M,K] @ B[K,N] + bias  (A,B given as bf16 hi/lo planes)
// CTA 128x128, 256 thr = 8 warps (4x2 of 32x64 warp tiles), BK=16, cp.async double buffer.
template<bool GELU, bool RES, bool SPLITOUT, bool WRITEF32>
__global__ __launch_bounds__(256) void bgemm_kernel(
    const __nv_bfloat16* __restrict__ Ahi, const __nv_bfloat16* __restrict__ Alo,
    const __nv_bfloat16* __restrict__ Bhi, const __nv_bfloat16* __restrict__ Blo,
    const float* __restrict__ bias, const float* __restrict__ res,
    float* __restrict__ C, __nv_bfloat16* __restrict__ Chi, __nv_bfloat16* __restrict__ Clo,
    int M, int N, int K)
{
    __shared__ __nv_bfloat16 sA[2][2][128][24];  // [stage][plane][row][k(16)+pad]
    __shared__ __nv_bfloat16 sB[2][2][16][136];  // [stage][plane][k][n(128)+pad]

    const int tid = threadIdx.x;
    const int warp = tid >> 5, lane = tid & 31;
    const int wr = warp >> 1, wc = warp & 1;
    const int m0 = blockIdx.y * 128, n0 = blockIdx.x * 128;
    const int nk = K >> 4;

    float acc[2][8][4];
#pragma unroll
    for (int mi = 0; mi < 2; ++mi)
#pragma unroll
        for (int ni = 0; ni < 8; ++ni)
#pragma unroll
            for (int r = 0; r < 4; ++r) acc[mi][ni][r] = 0.f;

    // copy assignments
    const int a_pl = tid >> 8;  // always 0 for first chunk; second chunk uses +256
    auto load_stage = [&](int st, int kt) {
        const int k0 = kt << 4;
#pragma unroll
        for (int c2 = 0; c2 < 2; ++c2) {
            int c = tid + c2 * 256;
            int pl = c >> 8, row = (c >> 1) & 127, kh = c & 1;
            const __nv_bfloat16* src = (pl ? Alo : Ahi) + (size_t)(m0 + row) * K + k0 + kh * 8;
            cpa16(&sA[st][pl][row][kh * 8], src);
        }
#pragma unroll
        for (int c2 = 0; c2 < 2; ++c2) {
            int c = tid + c2 * 256;
            int pl = c >> 8, kr = (c >> 4) & 15, nc = c & 15;
            const __nv_bfloat16* src = (pl ? Blo : Bhi) + (size_t)(k0 + kr) * N + n0 + nc * 8;
            cpa16(&sB[st][pl][kr][nc * 8], src);
        }
    };
    (void)a_pl;

    load_stage(0, 0);
    asm volatile("cp.async.commit_group;");

    const int arow = lane & 15;
    const int acol = (lane >> 4) * 8;
    const int krow = lane & 15;

    for (int kt = 0; kt < nk; ++kt) {
        const int st = kt & 1;
        if (kt + 1 < nk) {
            load_stage(st ^ 1, kt + 1);
            asm volatile("cp.async.commit_group;");
            asm volatile("cp.async.wait_group 1;");
        } else {
            asm volatile("cp.async.wait_group 0;");
        }
        __syncthreads();

        uint32_t ah[2][4], al[2][4];
#pragma unroll
        for (int mi = 0; mi < 2; ++mi) {
            ldsm4(ah[mi][0], ah[mi][1], ah[mi][2], ah[mi][3], &sA[st][0][wr * 32 + mi * 16 + arow][acol]);
            ldsm4(al[mi][0], al[mi][1], al[mi][2], al[mi][3], &sA[st][1][wr * 32 + mi * 16 + arow][acol]);
        }
#pragma unroll
        for (int np = 0; np < 4; ++np) {
            const int ncol = wc * 64 + np * 16 + ((lane & 16) ? 8 : 0);
            uint32_t bh[4], bl[4];
            ldsm4t(bh[0], bh[1], bh[2], bh[3], &sB[st][0][krow][ncol]);
            ldsm4t(bl[0], bl[1], bl[2], bl[3], &sB[st][1][krow][ncol]);
#pragma unroll
            for (int j = 0; j < 2; ++j) {
                const int ni = np * 2 + j;
#pragma unroll
                for (int mi = 0; mi < 2; ++mi) {
                    mma16816(acc[mi][ni], ah[mi], bh[2 * j], bh[2 * j + 1]);
                    mma16816(acc[mi][ni], ah[mi], bl[2 * j], bl[2 * j + 1]);
                    mma16816(acc[mi][ni], al[mi], bh[2 * j], bh[2 * j + 1]);
                }
            }
        }
        __syncthreads();
    }

    // epilogue
#pragma unroll
    for (int mi = 0; mi < 2; ++mi) {
        const int rbase = m0 + wr * 32 + mi * 16 + (lane >> 2);
#pragma unroll
        for (int ni = 0; ni < 8; ++ni) {
            const int cbase = n0 + wc * 64 + ni * 8 + (lane & 3) * 2;
            const float b0 = bias[cbase], b1 = bias[cbase + 1];
#pragma unroll
            for (int hrow = 0; hrow < 2; ++hrow) {
                const int row = rbase + hrow * 8;
                float v0 = acc[mi][ni][hrow * 2 + 0] + b0;
                float v1 = acc[mi][ni][hrow * 2 + 1] + b1;
                if (RES) {
                    v0 += res[(size_t)row * N + cbase];
                    v1 += res[(size_t)row * N + cbase + 1];
                }
                if (GELU) {
                    float u = v0;
                    v0 = 0.5f * u * (1.0f + tanhf(0.7978845608028654f * (u + 0.044715f * u * u * u)));
                    u = v1;
                    v1 = 0.5f * u * (1.0f + tanhf(0.7978845608028654f * (u + 0.044715f * u * u * u)));
                }
                const size_t idx = (size_t)row * N + cbase;
                if (WRITEF32) {
                    C[idx] = v0; C[idx + 1] = v1;
                }
                if (SPLITOUT) {
                    __nv_bfloat16 h0 = __float2bfloat16(v0);
                    __nv_bfloat16 h1 = __float2bfloat16(v1);
                    Chi[idx] = h0; Chi[idx + 1] = h1;
                    Clo[idx]     = __float2bfloat16(v0 - __bfloat162float(h0));
                    Clo[idx + 1] = __float2bfloat16(v1 - __bfloat162float(h1));
                }
            }
        }
    }
}

// ---------------- LayerNorm (fused bf16 split output) ----------------
__global__ __launch_bounds__(256) void ln_kernel(
    const float* __restrict__ in, const float* __restrict__ gamma,
    const float* __restrict__ beta, float* __restrict__ out,
    __nv_bfloat16* __restrict__ ohi, __nv_bfloat16* __restrict__ olo,
    const float* __restrict__ pos, const float* __restrict__ tok)
{
    const int r = blockIdx.x;
    const int s = r % S_;
    const int t = threadIdx.x;
    const float* row = in + (size_t)r * D_;
    float x[3];
#pragma unroll
    for (int j = 0; j < 3; ++j) {
        int i = t + j * 256;
        float v = row[i];
        if (pos) v += pos[(size_t)s * D_ + i] + tok[i];
        x[j] = v;
    }
    float sum = x[0] + x[1] + x[2];
    float sq  = x[0] * x[0] + x[1] * x[1] + x[2] * x[2];
    __shared__ float rs[8], rq[8];
#pragma unroll
    for (int o = 16; o > 0; o >>= 1) {
        sum += __shfl_xor_sync(0xffffffffu, sum, o);
        sq  += __shfl_xor_sync(0xffffffffu, sq, o);
    }
    if ((t & 31) == 0) { rs[t >> 5] = sum; rq[t >> 5] = sq; }
    __syncthreads();
    if (t < 32) {
        float s2 = (t < 8) ? rs[t] : 0.f;
        float q2 = (t < 8) ? rq[t] : 0.f;
#pragma unroll
        for (int o = 4; o > 0; o >>= 1) {
            s2 += __shfl_xor_sync(0xffffffffu, s2, o);
            q2 += __shfl_xor_sync(0xffffffffu, q2, o);
        }
        if (t == 0) { rs[0] = s2; rq[0] = q2; }
    }
    __syncthreads();
    const float mean = rs[0] * (1.0f / 768.0f);
    float var = rq[0] * (1.0f / 768.0f) - mean * mean;
    const float rstd = rsqrtf(fmaxf(var, 0.f) + 1e-12f);
#pragma unroll
    for (int j = 0; j < 3; ++j) {
        int i = t + j * 256;
        float y = (x[j] - mean) * rstd * gamma[i] + beta[i];
        size_t idx = (size_t)r * D_ + i;
        out[idx] = y;
        __nv_bfloat16 h = __float2bfloat16(y);
        ohi[idx] = h;
        olo[idx] = __float2bfloat16(y - __bfloat162float(h));
    }
}

// ---------------- fused block-sparse attention ----------------
// grid (78, H, B): idx<62 -> mid block qb=idx+1 (8 gathered tiles, full softmax).
// idx>=62 -> edge block slices: 8 CTAs per edge block, 8 consecutive key tiles each,
// writing partial (acc,m,l) to g_part for the merge kernel.
__global__ __launch_bounds__(256) void attn_kernel(
    const float* __restrict__ q, const float* __restrict__ k,
    const float* __restrict__ v, const float* __restrict__ mask)
{
    const int b = blockIdx.z, hh = blockIdx.y, ib = blockIdx.x;
    const int tid = threadIdx.x;
    const int r = tid >> 2, t4 = tid & 3;

    int qb, t0 = 0, e = 0, slice = 0;
    bool edge;
    if (ib < 62) { qb = ib + 1; edge = false; }
    else {
        edge = true;
        int xx = ib - 62;
        e = xx >> 3; slice = xx & 7;
        qb = e ? (NB_ - 1) : 0;
        t0 = slice * 8;
    }

    __shared__ float qs[64 * 64];   // Q^T
    __shared__ float kps[64 * 64];  // K^T then P^T
    __shared__ float vs[64 * 64];   // V

    {
        const int row = tid >> 2, dq = tid & 3;
        const float* qp = q + ((size_t)(b * S_ + qb * 64 + row)) * D_ + hh * 64 + dq * 16;
#pragma unroll
        for (int j = 0; j < 4; ++j) {
            float4 tq = *(const float4*)(qp + j * 4);
            int d = dq * 16 + j * 4;
            qs[(d + 0) * 64 + row] = tq.x;
            qs[(d + 1) * 64 + row] = tq.y;
            qs[(d + 2) * 64 + row] = tq.z;
            qs[(d + 3) * 64 + row] = tq.w;
        }
    }

    float acc[16];
#pragma unroll
    for (int i = 0; i < 16; ++i) acc[i] = 0.f;
    float m_run = -1e30f, l_run = 0.f;

    for (int kt = 0; kt < 8; ++kt) {
        const int kb = edge ? (t0 + kt) : g_gi[qb * 8 + kt];
        __syncthreads();
        {
            const int row = tid >> 2, dq = tid & 3;
            const float* kp = k + ((size_t)(b * S_ + kb * 64 + row)) * D_ + hh * 64 + dq * 16;
            const float* vp = v + ((size_t)(b * S_ + kb * 64 + row)) * D_ + hh * 64 + dq * 16;
#pragma unroll
            for (int j = 0; j < 4; ++j) {
                int d = dq * 16 + j * 4;
                float4 tk = *(const float4*)(kp + j * 4);
                kps[(d + 0) * 64 + row] = tk.x;
                kps[(d + 1) * 64 + row] = tk.y;
                kps[(d + 2) * 64 + row] = tk.z;
                kps[(d + 3) * 64 + row] = tk.w;
                *(float4*)&vs[row * 64 + d] = *(const float4*)(vp + j * 4);
            }
        }
        __syncthreads();

        float sc[16];
#pragma unroll
        for (int i = 0; i < 16; ++i) sc[i] = 0.f;
#pragma unroll 8
        for (int kk = 0; kk < 64; ++kk) {
            float qv = qs[kk * 64 + r];
#pragma unroll
            for (int i = 0; i < 16; ++i) sc[i] += qv * kps[kk * 64 + t4 * 16 + i];
        }
        const float* mrow = mask + (size_t)b * S_ + kb * 64 + t4 * 16;
        float tm = -1e30f;
#pragma unroll
        for (int i = 0; i < 16; ++i) {
            sc[i] = sc[i] * 0.125f - 1e9f * (1.0f - mrow[i]);
            tm = fmaxf(tm, sc[i]);
        }
        tm = fmaxf(tm, __shfl_xor_sync(0xffffffffu, tm, 1));
        tm = fmaxf(tm, __shfl_xor_sync(0xffffffffu, tm, 2));
        const float m_new = fmaxf(m_run, tm);
        const float corr = __expf(m_run - m_new);
        float psum = 0.f;
#pragma unroll
        for (int i = 0; i < 16; ++i) {
            sc[i] = __expf(sc[i] - m_new);
            psum += sc[i];
        }
        psum += __shfl_xor_sync(0xffffffffu, psum, 1);
        psum += __shfl_xor_sync(0xffffffffu, psum, 2);
        l_run = l_run * corr + psum;
        m_run = m_new;
#pragma unroll
        for (int i = 0; i < 16; ++i) acc[i] *= corr;

        __syncthreads();
#pragma unroll
        for (int i = 0; i < 16; ++i) kps[(t4 * 16 + i) * 64 + r] = sc[i];
        __syncthreads();

#pragma unroll 4
        for (int kk = 0; kk < 64; ++kk) {
            float p = kps[kk * 64 + r];
            const float4 v0 = *(const float4*)&vs[kk * 64 + t4 * 16];
            const float4 v1 = *(const float4*)&vs[kk * 64 + t4 * 16 + 4];
            const float4 v2 = *(const float4*)&vs[kk * 64 + t4 * 16 + 8];
            const float4 v3 = *(const float4*)&vs[kk * 64 + t4 * 16 + 12];
            acc[0]  += p * v0.x; acc[1]  += p * v0.y; acc[2]  += p * v0.z; acc[3]  += p * v0.w;
            acc[4]  += p * v1.x; acc[5]  += p * v1.y; acc[6]  += p * v1.z; acc[7]  += p * v1.w;
            acc[8]  += p * v2.x; acc[9]  += p * v2.y; acc[10] += p * v2.z; acc[11] += p * v2.w;
            acc[12] += p * v3.x; acc[13] += p * v3.y; acc[14] += p * v3.z; acc[15] += p * v3.w;
        }
    }

    if (!edge) {
        const float inv = 1.0f / l_run;
        const size_t idx = ((size_t)(b * S_ + qb * 64 + r)) * D_ + hh * 64 + t4 * 16;
#pragma unroll
        for (int i = 0; i < 16; ++i) {
            float vv = acc[i] * inv;
            __nv_bfloat16 h = __float2bfloat16(vv);
            g_chi[idx + i] = h;
            g_clo[idx + i] = __float2bfloat16(vv - __bfloat162float(h));
        }
    } else {
        float* pp = g_part + ((size_t)((((b * H_ + hh) * 2 + e) * 8 + slice) * 64 + r)) * 66;
#pragma unroll
        for (int i = 0; i < 16; ++i) pp[t4 * 16 + i] = acc[i];
        if (t4 == 0) { pp[64] = m_run; pp[65] = l_run; }
    }
}

// merge the 8 partial slices for each edge block row
__global__ __launch_bounds__(256) void merge_kernel() {
    const int e = blockIdx.x, hh = blockIdx.y, b = blockIdx.z;
    const int tid = threadIdx.x;
    const int r = tid >> 2, t4 = tid & 3;
    const size_t base = ((size_t)(((b * H_ + hh) * 2 + e) * 8)) * 64 * 66;

    float M = -1e30f;
#pragma unroll
    for (int s = 0; s < 8; ++s) M = fmaxf(M, g_part[base + ((size_t)s * 64 + r) * 66 + 64]);
    float L = 0.f;
    float acc[16];
#pragma unroll
    for (int i = 0; i < 16; ++i) acc[i] = 0.f;
#pragma unroll
    for (int s = 0; s < 8; ++s) {
        const float* pp = g_part + base + ((size_t)s * 64 + r) * 66;
        const float w = __expf(pp[64] - M);
        L += pp[65] * w;
#pragma unroll
        for (int i = 0; i < 16; ++i) acc[i] += pp[t4 * 16 + i] * w;
    }
    const float inv = 1.0f / L;
    const int qb = e ? (NB_ - 1) : 0;
    const size_t idx = ((size_t)(b * S_ + qb * 64 + r)) * D_ + hh * 64 + t4 * 16;
#pragma unroll
    for (int i = 0; i < 16; ++i) {
        float vv = acc[i] * inv;
        __nv_bfloat16 h = __float2bfloat16(vv);
        g_chi[idx + i] = h;
        g_clo[idx + i] = __float2bfloat16(vv - __bfloat162float(h));
    }
}

// ---------------- classifier ----------------
__global__ void cls1_kernel(const float* __restrict__ h, const float* __restrict__ w,
                            const float* __restrict__ bias, float* __restrict__ out)
{
    int gid = blockIdx.x * blockDim.x + threadIdx.x;
    if (gid >= 2 * 512) return;
    int b = gid >> 9, n = gid & 511;
    const float* hrow = h + (size_t)b * S_ * D_;
    float s = 0.f;
    for (int k2 = 0; k2 < D_; ++k2) s += hrow[k2] * w[(size_t)k2 * 512 + n];
    s += bias[n];
    out[gid] = fmaxf(s, 0.f);
}

__global__ void cls2_kernel(const float* __restrict__ rin, const float* __restrict__ w,
                            const float* __restrict__ bias, float* __restrict__ out)
{
    int gid = blockIdx.x * blockDim.x + threadIdx.x;
    if (gid >= 2 * TGT_) return;
    int b = gid >> 10, n = gid & 1023;
    float s = 0.f;
    for (int k2 = 0; k2 < 512; ++k2) s += rin[b * 512 + k2] * w[(size_t)k2 * TGT_ + n];
    out[gid] = s + bias[n];
}

// ---------------- host orchestration ----------------
extern "C" void kernel_launch(void* const* d_in, const int* in_sizes, int n_in,
                              void* d_out, int out_size)
{
    const float* x        = (const float*)d_in[0];
    const float* mask     = (const float*)d_in[1];
    const float* proj_w   = (const float*)d_in[2];
    const float* proj_b   = (const float*)d_in[3];
    const float* pos_emb  = (const float*)d_in[4];
    const float* tok_emb  = (const float*)d_in[5];
    const float* emb_g    = (const float*)d_in[6];
    const float* emb_b    = (const float*)d_in[7];
    const float* bq_all   = (const float*)d_in[9];
    const float* bk_all   = (const float*)d_in[11];
    const float* bv_all   = (const float*)d_in[13];
    const float* bo_all   = (const float*)d_in[15];
    const float* ln1g_all = (const float*)d_in[16];
    const float* ln1b_all = (const float*)d_in[17];
    const float* bi_all   = (const float*)d_in[19];
    const float* bo2_all  = (const float*)d_in[21];
    const float* ln2g_all = (const float*)d_in[22];
    const float* ln2b_all = (const float*)d_in[23];
    const float* cls_w1   = (const float*)d_in[24];
    const float* cls_b1   = (const float*)d_in[25];
    const float* cls_w2   = (const float*)d_in[26];
    const float* cls_b2   = (const float*)d_in[27];
    const int*   rb       = (const int*)d_in[28];
    float* out = (float*)d_out;

    float *ph, *pq, *pk, *pv, *ptmp, *pcls;
    __nv_bfloat16 *pwhi, *pwlo, *pxhi, *pxlo, *phhi, *phlo, *pchi, *pclo, *pfhi, *pflo;
    cudaGetSymbolAddress((void**)&ph,   g_h);
    cudaGetSymbolAddress((void**)&pq,   g_q);
    cudaGetSymbolAddress((void**)&pk,   g_k);
    cudaGetSymbolAddress((void**)&pv,   g_v);
    cudaGetSymbolAddress((void**)&ptmp, g_tmp);
    cudaGetSymbolAddress((void**)&pcls, g_cls);
    cudaGetSymbolAddress((void**)&pwhi, g_whi);
    cudaGetSymbolAddress((void**)&pwlo, g_wlo);
    cudaGetSymbolAddress((void**)&pxhi, g_xhi);
    cudaGetSymbolAddress((void**)&pxlo, g_xlo);
    cudaGetSymbolAddress((void**)&phhi, g_hhi);
    cudaGetSymbolAddress((void**)&phlo, g_hlo);
    cudaGetSymbolAddress((void**)&pchi, g_chi);
    cudaGetSymbolAddress((void**)&pclo, g_clo);
    cudaGetSymbolAddress((void**)&pfhi, g_fhi);
    cudaGetSymbolAddress((void**)&pflo, g_flo);

    // split all weights + input into bf16 hi/lo planes
    auto split = [&](const float* src, __nv_bfloat16* hi, __nv_bfloat16* lo, int n) {
        split_kernel<<<(n + 255) / 256, 256>>>(src, hi, lo, n);
    };
    split((const float*)d_in[2],  pwhi + OFF_PROJ, pwlo + OFF_PROJ, WN_PROJ);
    split((const float*)d_in[8],  pwhi + OFF_WQ,   pwlo + OFF_WQ,   WN_DD);
    split((const float*)d_in[10], pwhi + OFF_WK,   pwlo + OFF_WK,   WN_DD);
    split((const float*)d_in[12], pwhi + OFF_WV,   pwlo + OFF_WV,   WN_DD);
    split((const float*)d_in[14], pwhi + OFF_WO,   pwlo + OFF_WO,   WN_DD);
    split((const float*)d_in[18], pwhi + OFF_WI,   pwlo + OFF_WI,   WN_DF);
    split((const float*)d_in[20], pwhi + OFF_WO2,  pwlo + OFF_WO2,  WN_DF);
    split(x, pxhi, pxlo, T_ * IN_);
    build_gi_kernel<<<1, 64>>>(rb);
    (void)proj_w;

    const dim3 gD(D_ / 128, T_ / 128);
    const dim3 gF(FF_ / 128, T_ / 128);
    const dim3 gA(78, H_, B_);
    const dim3 gM(2, H_, B_);

    // embedding
    bgemm_kernel<false, false, false, true><<<gD, 256>>>(
        pxhi, pxlo, pwhi + OFF_PROJ, pwlo + OFF_PROJ, proj_b, nullptr,
        ptmp, nullptr, nullptr, T_, D_, IN_);
    ln_kernel<<<T_, 256>>>(ptmp, emb_g, emb_b, ph, phhi, phlo, pos_emb, tok_emb);

    for (int l = 0; l < L_; ++l) {
        const size_t odd = (size_t)l * D_ * D_;
        const size_t odf = (size_t)l * D_ * FF_;

        bgemm_kernel<false, false, false, true><<<gD, 256>>>(
            phhi, phlo, pwhi + OFF_WQ + odd, pwlo + OFF_WQ + odd, bq_all + (size_t)l * D_,
            nullptr, pq, nullptr, nullptr, T_, D_, D_);
        bgemm_kernel<false, false, false, true><<<gD, 256>>>(
            phhi, phlo, pwhi + OFF_WK + odd, pwlo + OFF_WK + odd, bk_all + (size_t)l * D_,
            nullptr, pk, nullptr, nullptr, T_, D_, D_);
        bgemm_kernel<false, false, false, true><<<gD, 256>>>(
            phhi, phlo, pwhi + OFF_WV + odd, pwlo + OFF_WV + odd, bv_all + (size_t)l * D_,
            nullptr, pv, nullptr, nullptr, T_, D_, D_);

        attn_kernel<<<gA, 256>>>(pq, pk, pv, mask);
        merge_kernel<<<gM, 256>>>();

        bgemm_kernel<false, true, false, true><<<gD, 256>>>(
            pchi, pclo, pwhi + OFF_WO + odd, pwlo + OFF_WO + odd, bo_all + (size_t)l * D_,
            ph, ptmp, nullptr, nullptr, T_, D_, D_);
        ln_kernel<<<T_, 256>>>(ptmp, ln1g_all + (size_t)l * D_, ln1b_all + (size_t)l * D_,
                               ph, phhi, phlo, nullptr, nullptr);

        bgemm_kernel<true, false, true, false><<<gF, 256>>>(
            phhi, phlo, pwhi + OFF_WI + odf, pwlo + OFF_WI + odf, bi_all + (size_t)l * FF_,
            nullptr, nullptr, pfhi, pflo, T_, FF_, D_);
        bgemm_kernel<false, true, false, true><<<gD, 256>>>(
            pfhi, pflo, pwhi + OFF_WO2 + odf, pwlo + OFF_WO2 + odf, bo2_all + (size_t)l * D_,
            ph, ptmp, nullptr, nullptr, T_, D_, FF_);
        ln_kernel<<<T_, 256>>>(ptmp, ln2g_all + (size_t)l * D_, ln2b_all + (size_t)l * D_,
                               ph, phhi, phlo, nullptr, nullptr);
    }

    cls1_kernel<<<4, 256>>>(ph, cls_w1, cls_b1, pcls);
    cls2_kernel<<<8, 256>>>(pcls, cls_w2, cls_b2, out);
}

// round 5
// speedup vs baseline: 2.1909x; 1.0804x over previous
#include <cuda_runtime.h>
#include <cuda.h>
#include <cuda_bf16.h>
#include <math.h>
#include <stdint.h>

#define B_    2
#define S_    4096
#define T_    8192
#define IN_   1280
#define D_    768
#define H_    12
#define FF_   3072
#define L_    12
#define TGT_  1024
#define NB_   64

#define WN_PROJ (IN_*D_)
#define WN_DD   (L_*D_*D_)
#define WN_DF   (L_*D_*FF_)
#define OFF_PROJ 0
#define OFF_WQ  (OFF_PROJ + WN_PROJ)
#define OFF_WK  (OFF_WQ + WN_DD)
#define OFF_WV  (OFF_WK + WN_DD)
#define OFF_WO  (OFF_WV + WN_DD)
#define OFF_WI  (OFF_WO + WN_DD)
#define OFF_WO2 (OFF_WI + WN_DF)
#define WTOT    (OFF_WO2 + WN_DF)

#define GEMM_SMEM 133120

// ---------------- scratch ----------------
__device__ float g_h[T_ * D_];
__device__ float g_q[T_ * D_];
__device__ float g_k[T_ * D_];
__device__ float g_v[T_ * D_];
__device__ float g_tmp[T_ * D_];
__device__ float g_cls[2 * 512];
__device__ int   g_gi[NB_ * 8];

__device__ __align__(128) __nv_bfloat16 g_whi[WTOT];
__device__ __align__(128) __nv_bfloat16 g_wlo[WTOT];
__device__ __align__(128) __nv_bfloat16 g_xhi[T_ * IN_];
__device__ __align__(128) __nv_bfloat16 g_xlo[T_ * IN_];
__device__ __align__(128) __nv_bfloat16 g_hhi[T_ * D_];
__device__ __align__(128) __nv_bfloat16 g_hlo[T_ * D_];
__device__ __align__(128) __nv_bfloat16 g_chi[T_ * D_];
__device__ __align__(128) __nv_bfloat16 g_clo[T_ * D_];
__device__ __align__(128) __nv_bfloat16 g_fhi[T_ * FF_];
__device__ __align__(128) __nv_bfloat16 g_flo[T_ * FF_];
__device__ float g_part[B_ * H_ * 2 * 8 * 64 * 66];

// ---------------- PTX helpers ----------------
__device__ __forceinline__ uint32_t s2u(const void* p) { return (uint32_t)__cvta_generic_to_shared(p); }
__device__ __forceinline__ void mbar_init(uint32_t a, uint32_t c) {
    asm volatile("mbarrier.init.shared.b64 [%0], %1;" :: "r"(a), "r"(c) : "memory");
}
__device__ __forceinline__ void mbar_expect(uint32_t a, uint32_t b) {
    asm volatile("mbarrier.arrive.expect_tx.shared.b64 _, [%0], %1;" :: "r"(a), "r"(b) : "memory");
}
__device__ __forceinline__ void mbar_wait(uint32_t a, uint32_t par) {
    asm volatile("{\n\t.reg .pred P;\n\tW_%=:\n\t"
                 "mbarrier.try_wait.parity.acquire.cta.shared::cta.b64 P, [%0], %1, 0x989680;\n\t"
                 "@P bra.uni D_%=;\n\tbra.uni W_%=;\n\tD_%=:\n\t}" :: "r"(a), "r"(par) : "memory");
}
__device__ __forceinline__ void tma2d(uint32_t dst, const void* tm, int x, int y, uint32_t mb) {
    asm volatile("cp.async.bulk.tensor.2d.shared::cta.global.tile.mbarrier::complete_tx::bytes "
                 "[%0], [%1, {%2, %3}], [%4];" :: "r"(dst), "l"(tm), "r"(x), "r"(y), "r"(mb) : "memory");
}
__device__ __forceinline__ void tma3d(uint32_t dst, const void* tm, int x, int y, int z, uint32_t mb) {
    asm volatile("cp.async.bulk.tensor.3d.shared::cta.global.tile.mbarrier::complete_tx::bytes "
                 "[%0], [%1, {%2, %3, %4}], [%5];" :: "r"(dst), "l"(tm), "r"(x), "r"(y), "r"(z), "r"(mb) : "memory");
}
__device__ __forceinline__ void ldsm4a(uint32_t* r, uint32_t a) {
    asm volatile("ldmatrix.sync.aligned.m8n8.x4.shared.b16 {%0,%1,%2,%3}, [%4];"
                 : "=r"(r[0]), "=r"(r[1]), "=r"(r[2]), "=r"(r[3]) : "r"(a));
}
__device__ __forceinline__ void mma16816(float* d, const uint32_t* a, uint32_t b0, uint32_t b1) {
    asm volatile("mma.sync.aligned.m16n8k16.row.col.f32.bf16.bf16.f32 "
                 "{%0,%1,%2,%3}, {%4,%5,%6,%7}, {%8,%9}, {%0,%1,%2,%3};"
                 : "+f"(d[0]), "+f"(d[1]), "+f"(d[2]), "+f"(d[3])
                 : "r"(a[0]), "r"(a[1]), "r"(a[2]), "r"(a[3]), "r"(b0), "r"(b1));
}

// ---------------- split / transpose-split / gather list ----------------
__global__ void split_kernel(const float* __restrict__ s, __nv_bfloat16* __restrict__ hi,
                             __nv_bfloat16* __restrict__ lo, int n) {
    int i = blockIdx.x * blockDim.x + threadIdx.x;
    if (i >= n) return;
    float v = s[i];
    __nv_bfloat16 h = __float2bfloat16(v);
    hi[i] = h;
    lo[i] = __float2bfloat16(v - __bfloat162float(h));
}

__global__ void tsplit_kernel(const float* __restrict__ src, __nv_bfloat16* __restrict__ hi,
                              __nv_bfloat16* __restrict__ lo, int K, int N) {
    __shared__ float t[32][33];
    const int l = blockIdx.z;
    const int n0 = blockIdx.x * 32, k0 = blockIdx.y * 32;
    const float* S = src + (size_t)l * K * N;
    const int tx = threadIdx.x, ty = threadIdx.y;
#pragma unroll
    for (int j = 0; j < 4; ++j)
        t[ty + j * 8][tx] = S[(size_t)(k0 + ty + j * 8) * N + n0 + tx];
    __syncthreads();
    __nv_bfloat16* Ht = hi + (size_t)l * K * N;
    __nv_bfloat16* Lt = lo + (size_t)l * K * N;
#pragma unroll
    for (int j = 0; j < 4; ++j) {
        int n = n0 + ty + j * 8;
        float v = t[tx][ty + j * 8];
        __nv_bfloat16 h = __float2bfloat16(v);
        Ht[(size_t)n * K + k0 + tx] = h;
        Lt[(size_t)n * K + k0 + tx] = __float2bfloat16(v - __bfloat162float(h));
    }
}

__global__ void build_gi_kernel(const int* __restrict__ rb) {
    int n = threadIdx.x;
    if (n < 1 || n >= NB_ - 1) return;
    int* p = g_gi + n * 8;
    p[0] = 0; p[1] = n - 1; p[2] = n; p[3] = n + 1; p[4] = NB_ - 1;
    p[5] = rb[n * 3 + 0]; p[6] = rb[n * 3 + 1]; p[7] = rb[n * 3 + 2];
}

// ---------------- TMA + mma.sync bf16x3 GEMM ----------------
// C[M=8192,N] = A[M,K] @ W[K,N] + bias (+res)(+gelu).
// A hi/lo [M,K] (2D TMA), W hi/lo transposed [L,N,K] (3D TMA). SW128 tiles, K64 chunks,
// double buffered. 256 thr = 8 warps (4x2 warptiles of 32x64). Thread 0 is the TMA producer.
template<bool GELU, bool RES, bool SPLITOUT, bool WRITEF32>
__global__ __launch_bounds__(256, 1) void tgemm_kernel(
    const __grid_constant__ CUtensorMap tAh, const __grid_constant__ CUtensorMap tAl,
    const __grid_constant__ CUtensorMap tBh, const __grid_constant__ CUtensorMap tBl,
    const float* __restrict__ bias, const float* __restrict__ res,
    float* __restrict__ C, __nv_bfloat16* __restrict__ Chi, __nv_bfloat16* __restrict__ Clo,
    int N, int K, int layer)
{
    extern __shared__ char dsm[];
    const uint32_t ctl = s2u(dsm);
    const uint32_t tiles = (ctl + 64 + 1023) & ~1023u;
    const int tid = threadIdx.x;
    const int warp = tid >> 5, lane = tid & 31;
    const int wr = warp >> 1, wc = warp & 1;
    const int m0 = blockIdx.y * 128, n0 = blockIdx.x * 128;
    const int nch = K >> 6;

    if (tid == 0) {
        mbar_init(ctl, 1);
        mbar_init(ctl + 8, 1);
        asm volatile("fence.proxy.async.shared::cta;" ::: "memory");
    }
    __syncthreads();

    auto issue = [&](int i) {
        const int st = i & 1;
        const uint32_t mb = ctl + st * 8;
        const uint32_t tb = tiles + st * 65536;
        mbar_expect(mb, 65536);
        const int k0 = i << 6;
        tma2d(tb +     0, &tAh, k0, m0, mb);
        tma2d(tb + 16384, &tAl, k0, m0, mb);
        tma3d(tb + 32768, &tBh, k0, n0, layer, mb);
        tma3d(tb + 49152, &tBl, k0, n0, layer, mb);
    };
    const bool prod = (tid == 0);
    if (prod) { issue(0); issue(1); }

    float acc[2][8][4];
#pragma unroll
    for (int mi = 0; mi < 2; ++mi)
#pragma unroll
        for (int ni = 0; ni < 8; ++ni)
#pragma unroll
            for (int r = 0; r < 4; ++r) acc[mi][ni][r] = 0.f;

    // per-lane ldmatrix address components (row*128 and swizzle xor)
    const int lrow = lane & 15;
    const uint32_t hb16 = (lane >> 4) * 16;
    uint32_t arow[2], axr[2], brow[4], bxr[4];
#pragma unroll
    for (int mi = 0; mi < 2; ++mi) {
        int r = wr * 32 + mi * 16 + lrow;
        arow[mi] = r * 128; axr[mi] = (r & 7) * 16;
    }
#pragma unroll
    for (int np = 0; np < 4; ++np) {
        int r = wc * 64 + np * 16 + lrow;
        brow[np] = r * 128; bxr[np] = (r & 7) * 16;
    }

    for (int i = 0; i < nch; ++i) {
        const int st = i & 1;
        mbar_wait(ctl + st * 8, (i >> 1) & 1);
        const uint32_t bAh = tiles + st * 65536;
        const uint32_t bAl = bAh + 16384;
        const uint32_t bBh = bAh + 32768;
        const uint32_t bBl = bAh + 49152;
#pragma unroll
        for (int ks = 0; ks < 4; ++ks) {
            const uint32_t colb = ks * 32 + hb16;
            uint32_t ah[2][4], al[2][4];
#pragma unroll
            for (int mi = 0; mi < 2; ++mi) {
                ldsm4a(ah[mi], bAh + arow[mi] + (colb ^ axr[mi]));
                ldsm4a(al[mi], bAl + arow[mi] + (colb ^ axr[mi]));
            }
#pragma unroll
            for (int np = 0; np < 4; ++np) {
                uint32_t bh[4], bl[4];
                ldsm4a(bh, bBh + brow[np] + (colb ^ bxr[np]));
                ldsm4a(bl, bBl + brow[np] + (colb ^ bxr[np]));
#pragma unroll
                for (int j = 0; j < 2; ++j) {
                    const int ni = np * 2 + j;
#pragma unroll
                    for (int mi = 0; mi < 2; ++mi) {
                        mma16816(acc[mi][ni], ah[mi], bh[j], bh[j + 2]);
                        mma16816(acc[mi][ni], ah[mi], bl[j], bl[j + 2]);
                        mma16816(acc[mi][ni], al[mi], bh[j], bh[j + 2]);
                    }
                }
            }
        }
        __syncthreads();
        if (prod && i + 2 < nch) issue(i + 2);
    }

    // epilogue
#pragma unroll
    for (int mi = 0; mi < 2; ++mi) {
        const int rbase = m0 + wr * 32 + mi * 16 + (lane >> 2);
#pragma unroll
        for (int ni = 0; ni < 8; ++ni) {
            const int cbase = n0 + wc * 64 + ni * 8 + (lane & 3) * 2;
            const float b0 = bias[cbase], b1 = bias[cbase + 1];
#pragma unroll
            for (int hr = 0; hr < 2; ++hr) {
                const int row = rbase + hr * 8;
                float v0 = acc[mi][ni][hr * 2 + 0] + b0;
                float v1 = acc[mi][ni][hr * 2 + 1] + b1;
                if (RES) {
                    v0 += res[(size_t)row * N + cbase];
                    v1 += res[(size_t)row * N + cbase + 1];
                }
                if (GELU) {
                    float u = v0;
                    v0 = 0.5f * u * (1.0f + tanhf(0.7978845608028654f * (u + 0.044715f * u * u * u)));
                    u = v1;
                    v1 = 0.5f * u * (1.0f + tanhf(0.7978845608028654f * (u + 0.044715f * u * u * u)));
                }
                const size_t idx = (size_t)row * N + cbase;
                if (WRITEF32) { C[idx] = v0; C[idx + 1] = v1; }
                if (SPLITOUT) {
                    __nv_bfloat16 h0 = __float2bfloat16(v0);
                    __nv_bfloat16 h1 = __float2bfloat16(v1);
                    Chi[idx] = h0; Chi[idx + 1] = h1;
                    Clo[idx]     = __float2bfloat16(v0 - __bfloat162float(h0));
                    Clo[idx + 1] = __float2bfloat16(v1 - __bfloat162float(h1));
                }
            }
        }
    }
}

// ---------------- LayerNorm (fused bf16 split output) ----------------
__global__ __launch_bounds__(256) void ln_kernel(
    const float* __restrict__ in, const float* __restrict__ gamma,
    const float* __restrict__ beta, float* __restrict__ out,
    __nv_bfloat16* __restrict__ ohi, __nv_bfloat16* __restrict__ olo,
    const float* __restrict__ pos, const float* __restrict__ tok)
{
    const int r = blockIdx.x, s = r % S_, t = threadIdx.x;
    const float* row = in + (size_t)r * D_;
    float x[3];
#pragma unroll
    for (int j = 0; j < 3; ++j) {
        int i = t + j * 256;
        float v = row[i];
        if (pos) v += pos[(size_t)s * D_ + i] + tok[i];
        x[j] = v;
    }
    float sum = x[0] + x[1] + x[2];
    float sq  = x[0] * x[0] + x[1] * x[1] + x[2] * x[2];
    __shared__ float rs[8], rq[8];
#pragma unroll
    for (int o = 16; o > 0; o >>= 1) {
        sum += __shfl_xor_sync(0xffffffffu, sum, o);
        sq  += __shfl_xor_sync(0xffffffffu, sq, o);
    }
    if ((t & 31) == 0) { rs[t >> 5] = sum; rq[t >> 5] = sq; }
    __syncthreads();
    if (t < 32) {
        float s2 = (t < 8) ? rs[t] : 0.f;
        float q2 = (t < 8) ? rq[t] : 0.f;
#pragma unroll
        for (int o = 4; o > 0; o >>= 1) {
            s2 += __shfl_xor_sync(0xffffffffu, s2, o);
            q2 += __shfl_xor_sync(0xffffffffu, q2, o);
        }
        if (t == 0) { rs[0] = s2; rq[0] = q2; }
    }
    __syncthreads();
    const float mean = rs[0] * (1.0f / 768.0f);
    float var = rq[0] * (1.0f / 768.0f) - mean * mean;
    const float rstd = rsqrtf(fmaxf(var, 0.f) + 1e-12f);
#pragma unroll
    for (int j = 0; j < 3; ++j) {
        int i = t + j * 256;
        float y = (x[j] - mean) * rstd * gamma[i] + beta[i];
        size_t idx = (size_t)r * D_ + i;
        out[idx] = y;
        __nv_bfloat16 h = __float2bfloat16(y);
        ohi[idx] = h;
        olo[idx] = __float2bfloat16(y - __bfloat162float(h));
    }
}

// ---------------- block-sparse attention (fp32 SIMT, balanced) ----------------
__global__ __launch_bounds__(256) void attn_kernel(
    const float* __restrict__ q, const float* __restrict__ k,
    const float* __restrict__ v, const float* __restrict__ mask)
{
    const int b = blockIdx.z, hh = blockIdx.y, ib = blockIdx.x;
    const int tid = threadIdx.x;
    const int r = tid >> 2, t4 = tid & 3;

    int qb, t0 = 0, e = 0, slice = 0;
    bool edge;
    if (ib < 62) { qb = ib + 1; edge = false; }
    else {
        edge = true;
        int xx = ib - 62;
        e = xx >> 3; slice = xx & 7;
        qb = e ? (NB_ - 1) : 0;
        t0 = slice * 8;
    }

    __shared__ float qs[64 * 64];
    __shared__ float kps[64 * 64];
    __shared__ float vs[64 * 64];

    {
        const int row = tid >> 2, dq = tid & 3;
        const float* qp = q + ((size_t)(b * S_ + qb * 64 + row)) * D_ + hh * 64 + dq * 16;
#pragma unroll
        for (int j = 0; j < 4; ++j) {
            float4 tq = *(const float4*)(qp + j * 4);
            int d = dq * 16 + j * 4;
            qs[(d + 0) * 64 + row] = tq.x;
            qs[(d + 1) * 64 + row] = tq.y;
            qs[(d + 2) * 64 + row] = tq.z;
            qs[(d + 3) * 64 + row] = tq.w;
        }
    }

    float acc[16];
#pragma unroll
    for (int i = 0; i < 16; ++i) acc[i] = 0.f;
    float m_run = -1e30f, l_run = 0.f;

    for (int kt = 0; kt < 8; ++kt) {
        const int kb = edge ? (t0 + kt) : g_gi[qb * 8 + kt];
        __syncthreads();
        {
            const int row = tid >> 2, dq = tid & 3;
            const float* kp = k + ((size_t)(b * S_ + kb * 64 + row)) * D_ + hh * 64 + dq * 16;
            const float* vp = v + ((size_t)(b * S_ + kb * 64 + row)) * D_ + hh * 64 + dq * 16;
#pragma unroll
            for (int j = 0; j < 4; ++j) {
                int d = dq * 16 + j * 4;
                float4 tk = *(const float4*)(kp + j * 4);
                kps[(d + 0) * 64 + row] = tk.x;
                kps[(d + 1) * 64 + row] = tk.y;
                kps[(d + 2) * 64 + row] = tk.z;
                kps[(d + 3) * 64 + row] = tk.w;
                *(float4*)&vs[row * 64 + d] = *(const float4*)(vp + j * 4);
            }
        }
        __syncthreads();

        float sc[16];
#pragma unroll
        for (int i = 0; i < 16; ++i) sc[i] = 0.f;
#pragma unroll 8
        for (int kk = 0; kk < 64; ++kk) {
            float qv = qs[kk * 64 + r];
#pragma unroll
            for (int i = 0; i < 16; ++i) sc[i] += qv * kps[kk * 64 + t4 * 16 + i];
        }
        const float* mrow = mask + (size_t)b * S_ + kb * 64 + t4 * 16;
        float tm = -1e30f;
#pragma unroll
        for (int i = 0; i < 16; ++i) {
            sc[i] = sc[i] * 0.125f - 1e9f * (1.0f - mrow[i]);
            tm = fmaxf(tm, sc[i]);
        }
        tm = fmaxf(tm, __shfl_xor_sync(0xffffffffu, tm, 1));
        tm = fmaxf(tm, __shfl_xor_sync(0xffffffffu, tm, 2));
        const float m_new = fmaxf(m_run, tm);
        const float corr = __expf(m_run - m_new);
        float psum = 0.f;
#pragma unroll
        for (int i = 0; i < 16; ++i) {
            sc[i] = __expf(sc[i] - m_new);
            psum += sc[i];
        }
        psum += __shfl_xor_sync(0xffffffffu, psum, 1);
        psum += __shfl_xor_sync(0xffffffffu, psum, 2);
        l_run = l_run * corr + psum;
        m_run = m_new;
#pragma unroll
        for (int i = 0; i < 16; ++i) acc[i] *= corr;

        __syncthreads();
#pragma unroll
        for (int i = 0; i < 16; ++i) kps[(t4 * 16 + i) * 64 + r] = sc[i];
        __syncthreads();

#pragma unroll 4
        for (int kk = 0; kk < 64; ++kk) {
            float p = kps[kk * 64 + r];
            const float4 v0 = *(const float4*)&vs[kk * 64 + t4 * 16];
            const float4 v1 = *(const float4*)&vs[kk * 64 + t4 * 16 + 4];
            const float4 v2 = *(const float4*)&vs[kk * 64 + t4 * 16 + 8];
            const float4 v3 = *(const float4*)&vs[kk * 64 + t4 * 16 + 12];
            acc[0]  += p * v0.x; acc[1]  += p * v0.y; acc[2]  += p * v0.z; acc[3]  += p * v0.w;
            acc[4]  += p * v1.x; acc[5]  += p * v1.y; acc[6]  += p * v1.z; acc[7]  += p * v1.w;
            acc[8]  += p * v2.x; acc[9]  += p * v2.y; acc[10] += p * v2.z; acc[11] += p * v2.w;
            acc[12] += p * v3.x; acc[13] += p * v3.y; acc[14] += p * v3.z; acc[15] += p * v3.w;
        }
    }

    if (!edge) {
        const float inv = 1.0f / l_run;
        const size_t idx = ((size_t)(b * S_ + qb * 64 + r)) * D_ + hh * 64 + t4 * 16;
#pragma unroll
        for (int i = 0; i < 16; ++i) {
            float vv = acc[i] * inv;
            __nv_bfloat16 h = __float2bfloat16(vv);
            g_chi[idx + i] = h;
            g_clo[idx + i] = __float2bfloat16(vv - __bfloat162float(h));
        }
    } else {
        float* pp = g_part + ((size_t)((((b * H_ + hh) * 2 + e) * 8 + slice) * 64 + r)) * 66;
#pragma unroll
        for (int i = 0; i < 16; ++i) pp[t4 * 16 + i] = acc[i];
        if (t4 == 0) { pp[64] = m_run; pp[65] = l_run; }
    }
}

__global__ __launch_bounds__(256) void merge_kernel() {
    const int e = blockIdx.x, hh = blockIdx.y, b = blockIdx.z;
    const int tid = threadIdx.x;
    const int r = tid >> 2, t4 = tid & 3;
    const size_t base = ((size_t)(((b * H_ + hh) * 2 + e) * 8)) * 64 * 66;

    float M = -1e30f;
#pragma unroll
    for (int s = 0; s < 8; ++s) M = fmaxf(M, g_part[base + ((size_t)s * 64 + r) * 66 + 64]);
    float L = 0.f, acc[16];
#pragma unroll
    for (int i = 0; i < 16; ++i) acc[i] = 0.f;
#pragma unroll
    for (int s = 0; s < 8; ++s) {
        const float* pp = g_part + base + ((size_t)s * 64 + r) * 66;
        const float w = __expf(pp[64] - M);
        L += pp[65] * w;
#pragma unroll
        for (int i = 0; i < 16; ++i) acc[i] += pp[t4 * 16 + i] * w;
    }
    const float inv = 1.0f / L;
    const int qb = e ? (NB_ - 1) : 0;
    const size_t idx = ((size_t)(b * S_ + qb * 64 + r)) * D_ + hh * 64 + t4 * 16;
#pragma unroll
    for (int i = 0; i < 16; ++i) {
        float vv = acc[i] * inv;
        __nv_bfloat16 h = __float2bfloat16(vv);
        g_chi[idx + i] = h;
        g_clo[idx + i] = __float2bfloat16(vv - __bfloat162float(h));
    }
}

// ---------------- classifier ----------------
__global__ void cls1_kernel(const float* __restrict__ h, const float* __restrict__ w,
                            const float* __restrict__ bias, float* __restrict__ out) {
    int gid = blockIdx.x * blockDim.x + threadIdx.x;
    if (gid >= 2 * 512) return;
    int b = gid >> 9, n = gid & 511;
    const float* hrow = h + (size_t)b * S_ * D_;
    float s = 0.f;
    for (int k2 = 0; k2 < D_; ++k2) s += hrow[k2] * w[(size_t)k2 * 512 + n];
    out[gid] = fmaxf(s + bias[n], 0.f);
}
__global__ void cls2_kernel(const float* __restrict__ rin, const float* __restrict__ w,
                            const float* __restrict__ bias, float* __restrict__ out) {
    int gid = blockIdx.x * blockDim.x + threadIdx.x;
    if (gid >= 2 * TGT_) return;
    int b = gid >> 10, n = gid & 1023;
    float s = 0.f;
    for (int k2 = 0; k2 < 512; ++k2) s += rin[b * 512 + k2] * w[(size_t)k2 * TGT_ + n];
    out[gid] = s + bias[n];
}

// ---------------- host ----------------
typedef CUresult (*EncFn)(CUtensorMap*, CUtensorMapDataType, cuuint32_t, void*,
                          const cuuint64_t*, const cuuint64_t*, const cuuint32_t*, const cuuint32_t*,
                          CUtensorMapInterleave, CUtensorMapSwizzle, CUtensorMapL2promotion,
                          CUtensorMapFloatOOBfill);

extern "C" void kernel_launch(void* const* d_in, const int* in_sizes, int n_in,
                              void* d_out, int out_size)
{
    const float* x        = (const float*)d_in[0];
    const float* mask     = (const float*)d_in[1];
    const float* proj_b   = (const float*)d_in[3];
    const float* pos_emb  = (const float*)d_in[4];
    const float* tok_emb  = (const float*)d_in[5];
    const float* emb_g    = (const float*)d_in[6];
    const float* emb_b    = (const float*)d_in[7];
    const float* bq_all   = (const float*)d_in[9];
    const float* bk_all   = (const float*)d_in[11];
    const float* bv_all   = (const float*)d_in[13];
    const float* bo_all   = (const float*)d_in[15];
    const float* ln1g_all = (const float*)d_in[16];
    const float* ln1b_all = (const float*)d_in[17];
    const float* bi_all   = (const float*)d_in[19];
    const float* bo2_all  = (const float*)d_in[21];
    const float* ln2g_all = (const float*)d_in[22];
    const float* ln2b_all = (const float*)d_in[23];
    const float* cls_w1   = (const float*)d_in[24];
    const float* cls_b1   = (const float*)d_in[25];
    const float* cls_w2   = (const float*)d_in[26];
    const float* cls_b2   = (const float*)d_in[27];
    const int*   rb       = (const int*)d_in[28];
    float* out = (float*)d_out;

    float *ph, *pq, *pk, *pv, *ptmp, *pcls;
    __nv_bfloat16 *pwhi, *pwlo, *pxhi, *pxlo, *phhi, *phlo, *pchi, *pclo, *pfhi, *pflo;
    cudaGetSymbolAddress((void**)&ph,   g_h);
    cudaGetSymbolAddress((void**)&pq,   g_q);
    cudaGetSymbolAddress((void**)&pk,   g_k);
    cudaGetSymbolAddress((void**)&pv,   g_v);
    cudaGetSymbolAddress((void**)&ptmp, g_tmp);
    cudaGetSymbolAddress((void**)&pcls, g_cls);
    cudaGetSymbolAddress((void**)&pwhi, g_whi);
    cudaGetSymbolAddress((void**)&pwlo, g_wlo);
    cudaGetSymbolAddress((void**)&pxhi, g_xhi);
    cudaGetSymbolAddress((void**)&pxlo, g_xlo);
    cudaGetSymbolAddress((void**)&phhi, g_hhi);
    cudaGetSymbolAddress((void**)&phlo, g_hlo);
    cudaGetSymbolAddress((void**)&pchi, g_chi);
    cudaGetSymbolAddress((void**)&pclo, g_clo);
    cudaGetSymbolAddress((void**)&pfhi, g_fhi);
    cudaGetSymbolAddress((void**)&pflo, g_flo);

    EncFn enc = nullptr;
    cudaDriverEntryPointQueryResult qr;
    cudaGetDriverEntryPointByVersion("cuTensorMapEncodeTiled", (void**)&enc, 12000,
                                     cudaEnableDefault, &qr);

    auto mk2 = [&](CUtensorMap* m, void* p, uint64_t K) {
        cuuint64_t d[2] = {K, T_};
        cuuint64_t st[1] = {K * 2};
        cuuint32_t bx[2] = {64, 128}, es[2] = {1, 1};
        enc(m, CU_TENSOR_MAP_DATA_TYPE_BFLOAT16, 2, p, d, st, bx, es,
            CU_TENSOR_MAP_INTERLEAVE_NONE, CU_TENSOR_MAP_SWIZZLE_128B,
            CU_TENSOR_MAP_L2_PROMOTION_L2_128B, CU_TENSOR_MAP_FLOAT_OOB_FILL_NONE);
    };
    auto mk3 = [&](CUtensorMap* m, void* p, uint64_t K, uint64_t N, uint64_t Lz) {
        cuuint64_t d[3] = {K, N, Lz};
        cuuint64_t st[2] = {K * 2, N * K * 2};
        cuuint32_t bx[3] = {64, 128, 1}, es[3] = {1, 1, 1};
        enc(m, CU_TENSOR_MAP_DATA_TYPE_BFLOAT16, 3, p, d, st, bx, es,
            CU_TENSOR_MAP_INTERLEAVE_NONE, CU_TENSOR_MAP_SWIZZLE_128B,
            CU_TENSOR_MAP_L2_PROMOTION_L2_128B, CU_TENSOR_MAP_FLOAT_OOB_FILL_NONE);
    };

    CUtensorMap mxh, mxl, mhh, mhl, mch, mcl, mfh, mfl;
    CUtensorMap mpjh, mpjl, mqh, mql, mkh, mkl, mvh, mvl, moh, mol, mih, mil, m2h, m2l;
    mk2(&mxh, pxhi, IN_); mk2(&mxl, pxlo, IN_);
    mk2(&mhh, phhi, D_);  mk2(&mhl, phlo, D_);
    mk2(&mch, pchi, D_);  mk2(&mcl, pclo, D_);
    mk2(&mfh, pfhi, FF_); mk2(&mfl, pflo, FF_);
    mk3(&mpjh, pwhi + OFF_PROJ, IN_, D_, 1);  mk3(&mpjl, pwlo + OFF_PROJ, IN_, D_, 1);
    mk3(&mqh, pwhi + OFF_WQ, D_, D_, L_);     mk3(&mql, pwlo + OFF_WQ, D_, D_, L_);
    mk3(&mkh, pwhi + OFF_WK, D_, D_, L_);     mk3(&mkl, pwlo + OFF_WK, D_, D_, L_);
    mk3(&mvh, pwhi + OFF_WV, D_, D_, L_);     mk3(&mvl, pwlo + OFF_WV, D_, D_, L_);
    mk3(&moh, pwhi + OFF_WO, D_, D_, L_);     mk3(&mol, pwlo + OFF_WO, D_, D_, L_);
    mk3(&mih, pwhi + OFF_WI, D_, FF_, L_);    mk3(&mil, pwlo + OFF_WI, D_, FF_, L_);
    mk3(&m2h, pwhi + OFF_WO2, FF_, D_, L_);   mk3(&m2l, pwlo + OFF_WO2, FF_, D_, L_);

    cudaFuncSetAttribute(tgemm_kernel<false, false, false, true>,
                         cudaFuncAttributeMaxDynamicSharedMemorySize, GEMM_SMEM);
    cudaFuncSetAttribute(tgemm_kernel<false, true, false, true>,
                         cudaFuncAttributeMaxDynamicSharedMemorySize, GEMM_SMEM);
    cudaFuncSetAttribute(tgemm_kernel<true, false, true, false>,
                         cudaFuncAttributeMaxDynamicSharedMemorySize, GEMM_SMEM);

    // prep: weight transpose-splits, x split, gather list
    dim3 tb(32, 8);
    tsplit_kernel<<<dim3(D_ / 32, IN_ / 32, 1), tb>>>((const float*)d_in[2],  pwhi + OFF_PROJ, pwlo + OFF_PROJ, IN_, D_);
    tsplit_kernel<<<dim3(D_ / 32, D_ / 32, L_), tb>>>((const float*)d_in[8],  pwhi + OFF_WQ, pwlo + OFF_WQ, D_, D_);
    tsplit_kernel<<<dim3(D_ / 32, D_ / 32, L_), tb>>>((const float*)d_in[10], pwhi + OFF_WK, pwlo + OFF_WK, D_, D_);
    tsplit_kernel<<<dim3(D_ / 32, D_ / 32, L_), tb>>>((const float*)d_in[12], pwhi + OFF_WV, pwlo + OFF_WV, D_, D_);
    tsplit_kernel<<<dim3(D_ / 32, D_ / 32, L_), tb>>>((const float*)d_in[14], pwhi + OFF_WO, pwlo + OFF_WO, D_, D_);
    tsplit_kernel<<<dim3(FF_ / 32, D_ / 32, L_), tb>>>((const float*)d_in[18], pwhi + OFF_WI, pwlo + OFF_WI, D_, FF_);
    tsplit_kernel<<<dim3(D_ / 32, FF_ / 32, L_), tb>>>((const float*)d_in[20], pwhi + OFF_WO2, pwlo + OFF_WO2, FF_, D_);
    split_kernel<<<(T_ * IN_ + 255) / 256, 256>>>(x, pxhi, pxlo, T_ * IN_);
    build_gi_kernel<<<1, 64>>>(rb);

    const dim3 gD(D_ / 128, T_ / 128);
    const dim3 gF(FF_ / 128, T_ / 128);
    const dim3 gA(78, H_, B_);
    const dim3 gM(2, H_, B_);

    tgemm_kernel<false, false, false, true><<<gD, 256, GEMM_SMEM>>>(
        mxh, mxl, mpjh, mpjl, proj_b, nullptr, ptmp, nullptr, nullptr, D_, IN_, 0);
    ln_kernel<<<T_, 256>>>(ptmp, emb_g, emb_b, ph, phhi, phlo, pos_emb, tok_emb);

    for (int l = 0; l < L_; ++l) {
        tgemm_kernel<false, false, false, true><<<gD, 256, GEMM_SMEM>>>(
            mhh, mhl, mqh, mql, bq_all + (size_t)l * D_, nullptr, pq, nullptr, nullptr, D_, D_, l);
        tgemm_kernel<false, false, false, true><<<gD, 256, GEMM_SMEM>>>(
            mhh, mhl, mkh, mkl, bk_all + (size_t)l * D_, nullptr, pk, nullptr, nullptr, D_, D_, l);
        tgemm_kernel<false, false, false, true><<<gD, 256, GEMM_SMEM>>>(
            mhh, mhl, mvh, mvl, bv_all + (size_t)l * D_, nullptr, pv, nullptr, nullptr, D_, D_, l);

        attn_kernel<<<gA, 256>>>(pq, pk, pv, mask);
        merge_kernel<<<gM, 256>>>();

        tgemm_kernel<false, true, false, true><<<gD, 256, GEMM_SMEM>>>(
            mch, mcl, moh, mol, bo_all + (size_t)l * D_, ph, ptmp, nullptr, nullptr, D_, D_, l);
        ln_kernel<<<T_, 256>>>(ptmp, ln1g_all + (size_t)l * D_, ln1b_all + (size_t)l * D_,
                               ph, phhi, phlo, nullptr, nullptr);

        tgemm_kernel<true, false, true, false><<<gF, 256, GEMM_SMEM>>>(
            mhh, mhl, mih, mil, bi_all + (size_t)l * FF_, nullptr, nullptr, pfhi, pflo, FF_, D_, l);
        tgemm_kernel<false, true, false, true><<<gD, 256, GEMM_SMEM>>>(
            mfh, mfl, m2h, m2l, bo2_all + (size_t)l * D_, ph, ptmp, nullptr, nullptr, D_, FF_, l);
        ln_kernel<<<T_, 256>>>(ptmp, ln2g_all + (size_t)l * D_, ln2b_all + (size_t)l * D_,
                               ph, phhi, phlo, nullptr, nullptr);
    }

    cls1_kernel<<<4, 256>>>(ph, cls_w1, cls_b1, pcls);
    cls2_kernel<<<8, 256>>>(pcls, cls_w2, cls_b2, out);
}

// round 6
// speedup vs baseline: 4.7571x; 2.1713x over previous
#include <cuda_runtime.h>
#include <cuda.h>
#include <cuda_bf16.h>
#include <math.h>
#include <stdint.h>

#define B_    2
#define S_    4096
#define T_    8192
#define IN_   1280
#define D_    768
#define H_    12
#define FF_   3072
#define L_    12
#define TGT_  1024
#define NB_   64
#define NQKV  2304

// weight arena (element offsets, [N,K] transposed planes)
#define OFF_PROJ 0
#define OFF_QKV  (IN_*D_)
#define OFF_WO   (OFF_QKV + L_*NQKV*D_)
#define OFF_WI   (OFF_WO + L_*D_*D_)
#define OFF_WO2  (OFF_WI + L_*D_*FF_)
#define WTOT     (OFF_WO2 + L_*FF_*D_)

#define GEMM_SMEM 133120
#define ATTN_SMEM 55296

// ---------------- scratch ----------------
__device__ float g_h[T_ * D_];
__device__ float g_tmp[T_ * D_];
__device__ float g_cls[2 * 512];
__device__ float g_bqkv[L_ * NQKV];
__device__ int   g_gi[NB_ * 8];

__device__ __align__(128) __nv_bfloat16 g_whi[WTOT];
__device__ __align__(128) __nv_bfloat16 g_wlo[WTOT];
__device__ __align__(128) __nv_bfloat16 g_xhi[T_ * IN_];
__device__ __align__(128) __nv_bfloat16 g_xlo[T_ * IN_];
__device__ __align__(128) __nv_bfloat16 g_hhi[T_ * D_];
__device__ __align__(128) __nv_bfloat16 g_hlo[T_ * D_];
__device__ __align__(128) __nv_bfloat16 g_chi[T_ * D_];
__device__ __align__(128) __nv_bfloat16 g_clo[T_ * D_];
__device__ __align__(128) __nv_bfloat16 g_fhi[T_ * FF_];
__device__ __align__(128) __nv_bfloat16 g_flo[T_ * FF_];
__device__ __align__(128) __nv_bfloat16 g_qkvhi[T_ * NQKV];
__device__ __align__(128) __nv_bfloat16 g_qkvlo[T_ * NQKV];
__device__ float g_part[B_ * H_ * 2 * 8 * 64 * 66];

// ---------------- PTX helpers ----------------
__device__ __forceinline__ uint32_t s2u(const void* p) { return (uint32_t)__cvta_generic_to_shared(p); }
__device__ __forceinline__ void mbar_init(uint32_t a, uint32_t c) {
    asm volatile("mbarrier.init.shared.b64 [%0], %1;" :: "r"(a), "r"(c) : "memory");
}
__device__ __forceinline__ void mbar_expect(uint32_t a, uint32_t b) {
    asm volatile("mbarrier.arrive.expect_tx.shared.b64 _, [%0], %1;" :: "r"(a), "r"(b) : "memory");
}
__device__ __forceinline__ void mbar_wait(uint32_t a, uint32_t par) {
    asm volatile("{\n\t.reg .pred P;\n\tW_%=:\n\t"
                 "mbarrier.try_wait.parity.acquire.cta.shared::cta.b64 P, [%0], %1, 0x989680;\n\t"
                 "@P bra.uni D_%=;\n\tbra.uni W_%=;\n\tD_%=:\n\t}" :: "r"(a), "r"(par) : "memory");
}
__device__ __forceinline__ void tma2d(uint32_t dst, const void* tm, int x, int y, uint32_t mb) {
    asm volatile("cp.async.bulk.tensor.2d.shared::cta.global.tile.mbarrier::complete_tx::bytes "
                 "[%0], [%1, {%2, %3}], [%4];" :: "r"(dst), "l"(tm), "r"(x), "r"(y), "r"(mb) : "memory");
}
__device__ __forceinline__ void tma3d(uint32_t dst, const void* tm, int x, int y, int z, uint32_t mb) {
    asm volatile("cp.async.bulk.tensor.3d.shared::cta.global.tile.mbarrier::complete_tx::bytes "
                 "[%0], [%1, {%2, %3, %4}], [%5];" :: "r"(dst), "l"(tm), "r"(x), "r"(y), "r"(z), "r"(mb) : "memory");
}
__device__ __forceinline__ void ldsm4a(uint32_t* r, uint32_t a) {
    asm volatile("ldmatrix.sync.aligned.m8n8.x4.shared.b16 {%0,%1,%2,%3}, [%4];"
                 : "=r"(r[0]), "=r"(r[1]), "=r"(r[2]), "=r"(r[3]) : "r"(a));
}
__device__ __forceinline__ void ldsm4t(uint32_t* r, uint32_t a) {
    asm volatile("ldmatrix.sync.aligned.m8n8.x4.trans.shared.b16 {%0,%1,%2,%3}, [%4];"
                 : "=r"(r[0]), "=r"(r[1]), "=r"(r[2]), "=r"(r[3]) : "r"(a));
}
__device__ __forceinline__ void mma16816(float* d, const uint32_t* a, uint32_t b0, uint32_t b1) {
    asm volatile("mma.sync.aligned.m16n8k16.row.col.f32.bf16.bf16.f32 "
                 "{%0,%1,%2,%3}, {%4,%5,%6,%7}, {%8,%9}, {%0,%1,%2,%3};"
                 : "+f"(d[0]), "+f"(d[1]), "+f"(d[2]), "+f"(d[3])
                 : "r"(a[0]), "r"(a[1]), "r"(a[2]), "r"(a[3]), "r"(b0), "r"(b1));
}
__device__ __forceinline__ uint32_t packbf2(float lo_e, float hi_e) {
    __nv_bfloat162 t;
    t.x = __float2bfloat16(lo_e);
    t.y = __float2bfloat16(hi_e);
    return *(uint32_t*)&t;
}

// ---------------- prep kernels ----------------
__global__ void split_kernel(const float* __restrict__ s, __nv_bfloat16* __restrict__ hi,
                             __nv_bfloat16* __restrict__ lo, int n) {
    int i = blockIdx.x * blockDim.x + threadIdx.x;
    if (i >= n) return;
    float v = s[i];
    __nv_bfloat16 h = __float2bfloat16(v);
    hi[i] = h;
    lo[i] = __float2bfloat16(v - __bfloat162float(h));
}

__global__ void tsplit_kernel(const float* __restrict__ src, __nv_bfloat16* __restrict__ hi,
                              __nv_bfloat16* __restrict__ lo, int K, int N, int lstride) {
    __shared__ float t[32][33];
    const int l = blockIdx.z;
    const int n0 = blockIdx.x * 32, k0 = blockIdx.y * 32;
    const float* S = src + (size_t)l * K * N;
    const int tx = threadIdx.x, ty = threadIdx.y;
#pragma unroll
    for (int j = 0; j < 4; ++j)
        t[ty + j * 8][tx] = S[(size_t)(k0 + ty + j * 8) * N + n0 + tx];
    __syncthreads();
    __nv_bfloat16* Ht = hi + (size_t)l * lstride;
    __nv_bfloat16* Lt = lo + (size_t)l * lstride;
#pragma unroll
    for (int j = 0; j < 4; ++j) {
        int n = n0 + ty + j * 8;
        float v = t[tx][ty + j * 8];
        __nv_bfloat16 h = __float2bfloat16(v);
        Ht[(size_t)n * K + k0 + tx] = h;
        Lt[(size_t)n * K + k0 + tx] = __float2bfloat16(v - __bfloat162float(h));
    }
}

__global__ void build_gi_kernel(const int* __restrict__ rb) {
    int n = threadIdx.x;
    if (n < 1 || n >= NB_ - 1) return;
    int* p = g_gi + n * 8;
    p[0] = 0; p[1] = n - 1; p[2] = n; p[3] = n + 1; p[4] = NB_ - 1;
    p[5] = rb[n * 3 + 0]; p[6] = rb[n * 3 + 1]; p[7] = rb[n * 3 + 2];
}

__global__ void bcat_kernel(const float* __restrict__ bq, const float* __restrict__ bk,
                            const float* __restrict__ bv) {
    int i = blockIdx.x * blockDim.x + threadIdx.x;
    if (i >= L_ * NQKV) return;
    int l = i / NQKV, n = i % NQKV;
    float v = (n < 768) ? bq[l * 768 + n] : (n < 1536) ? bk[l * 768 + n - 768] : bv[l * 768 + n - 1536];
    g_bqkv[i] = v;
}

// ---------------- TMA + mma.sync bf16x3 GEMM ----------------
template<bool GELU, bool RES, bool SPLITOUT, bool WRITEF32>
__global__ __launch_bounds__(256, 1) void tgemm_kernel(
    const __grid_constant__ CUtensorMap tAh, const __grid_constant__ CUtensorMap tAl,
    const __grid_constant__ CUtensorMap tBh, const __grid_constant__ CUtensorMap tBl,
    const float* __restrict__ bias, const float* __restrict__ res,
    float* __restrict__ C, __nv_bfloat16* __restrict__ Chi, __nv_bfloat16* __restrict__ Clo,
    int N, int K, int layer)
{
    extern __shared__ char dsm[];
    const uint32_t ctl = s2u(dsm);
    const uint32_t tiles = (ctl + 64 + 1023) & ~1023u;
    const int tid = threadIdx.x;
    const int warp = tid >> 5, lane = tid & 31;
    const int wr = warp >> 1, wc = warp & 1;
    const int m0 = blockIdx.y * 128, n0 = blockIdx.x * 128;
    const int nch = K >> 6;

    if (tid == 0) {
        mbar_init(ctl, 1);
        mbar_init(ctl + 8, 1);
        asm volatile("fence.proxy.async.shared::cta;" ::: "memory");
    }
    __syncthreads();

    auto issue = [&](int i) {
        const int st = i & 1;
        const uint32_t mb = ctl + st * 8;
        const uint32_t tb = tiles + st * 65536;
        mbar_expect(mb, 65536);
        const int k0 = i << 6;
        tma2d(tb +     0, &tAh, k0, m0, mb);
        tma2d(tb + 16384, &tAl, k0, m0, mb);
        tma3d(tb + 32768, &tBh, k0, n0, layer, mb);
        tma3d(tb + 49152, &tBl, k0, n0, layer, mb);
    };
    const bool prod = (tid == 0);
    if (prod) { issue(0); issue(1); }

    float acc[2][8][4];
#pragma unroll
    for (int mi = 0; mi < 2; ++mi)
#pragma unroll
        for (int ni = 0; ni < 8; ++ni)
#pragma unroll
            for (int r = 0; r < 4; ++r) acc[mi][ni][r] = 0.f;

    const int lrow = lane & 15;
    const uint32_t hb16 = (lane >> 4) * 16;
    uint32_t arow[2], axr[2], brow[4], bxr[4];
#pragma unroll
    for (int mi = 0; mi < 2; ++mi) {
        int r = wr * 32 + mi * 16 + lrow;
        arow[mi] = r * 128; axr[mi] = (r & 7) * 16;
    }
#pragma unroll
    for (int np = 0; np < 4; ++np) {
        int r = wc * 64 + np * 16 + lrow;
        brow[np] = r * 128; bxr[np] = (r & 7) * 16;
    }

    for (int i = 0; i < nch; ++i) {
        const int st = i & 1;
        mbar_wait(ctl + st * 8, (i >> 1) & 1);
        const uint32_t bAh = tiles + st * 65536;
        const uint32_t bAl = bAh + 16384;
        const uint32_t bBh = bAh + 32768;
        const uint32_t bBl = bAh + 49152;
#pragma unroll
        for (int ks = 0; ks < 4; ++ks) {
            const uint32_t colb = ks * 32 + hb16;
            uint32_t ah[2][4], al[2][4];
#pragma unroll
            for (int mi = 0; mi < 2; ++mi) {
                ldsm4a(ah[mi], bAh + arow[mi] + (colb ^ axr[mi]));
                ldsm4a(al[mi], bAl + arow[mi] + (colb ^ axr[mi]));
            }
#pragma unroll
            for (int np = 0; np < 4; ++np) {
                uint32_t bh[4], bl[4];
                ldsm4a(bh, bBh + brow[np] + (colb ^ bxr[np]));
                ldsm4a(bl, bBl + brow[np] + (colb ^ bxr[np]));
#pragma unroll
                for (int j = 0; j < 2; ++j) {
                    const int ni = np * 2 + j;
#pragma unroll
                    for (int mi = 0; mi < 2; ++mi) {
                        mma16816(acc[mi][ni], ah[mi], bh[j], bh[j + 2]);
                        mma16816(acc[mi][ni], ah[mi], bl[j], bl[j + 2]);
                        mma16816(acc[mi][ni], al[mi], bh[j], bh[j + 2]);
                    }
                }
            }
        }
        __syncthreads();
        if (prod && i + 2 < nch) issue(i + 2);
    }

#pragma unroll
    for (int mi = 0; mi < 2; ++mi) {
        const int rbase = m0 + wr * 32 + mi * 16 + (lane >> 2);
#pragma unroll
        for (int ni = 0; ni < 8; ++ni) {
            const int cbase = n0 + wc * 64 + ni * 8 + (lane & 3) * 2;
            const float b0 = bias[cbase], b1 = bias[cbase + 1];
#pragma unroll
            for (int hr = 0; hr < 2; ++hr) {
                const int row = rbase + hr * 8;
                float v0 = acc[mi][ni][hr * 2 + 0] + b0;
                float v1 = acc[mi][ni][hr * 2 + 1] + b1;
                if (RES) {
                    v0 += res[(size_t)row * N + cbase];
                    v1 += res[(size_t)row * N + cbase + 1];
                }
                if (GELU) {
                    float u = v0;
                    v0 = 0.5f * u * (1.0f + tanhf(0.7978845608028654f * (u + 0.044715f * u * u * u)));
                    u = v1;
                    v1 = 0.5f * u * (1.0f + tanhf(0.7978845608028654f * (u + 0.044715f * u * u * u)));
                }
                const size_t idx = (size_t)row * N + cbase;
                if (WRITEF32) { C[idx] = v0; C[idx + 1] = v1; }
                if (SPLITOUT) {
                    __nv_bfloat16 h0 = __float2bfloat16(v0);
                    __nv_bfloat16 h1 = __float2bfloat16(v1);
                    Chi[idx] = h0; Chi[idx + 1] = h1;
                    Clo[idx]     = __float2bfloat16(v0 - __bfloat162float(h0));
                    Clo[idx + 1] = __float2bfloat16(v1 - __bfloat162float(h1));
                }
            }
        }
    }
}

// ---------------- LayerNorm ----------------
__global__ __launch_bounds__(256) void ln_kernel(
    const float* __restrict__ in, const float* __restrict__ gamma,
    const float* __restrict__ beta, float* __restrict__ out,
    __nv_bfloat16* __restrict__ ohi, __nv_bfloat16* __restrict__ olo,
    const float* __restrict__ pos, const float* __restrict__ tok)
{
    const int r = blockIdx.x, s = r % S_, t = threadIdx.x;
    const float* row = in + (size_t)r * D_;
    float x[3];
#pragma unroll
    for (int j = 0; j < 3; ++j) {
        int i = t + j * 256;
        float v = row[i];
        if (pos) v += pos[(size_t)s * D_ + i] + tok[i];
        x[j] = v;
    }
    float sum = x[0] + x[1] + x[2];
    float sq  = x[0] * x[0] + x[1] * x[1] + x[2] * x[2];
    __shared__ float rs[8], rq[8];
#pragma unroll
    for (int o = 16; o > 0; o >>= 1) {
        sum += __shfl_xor_sync(0xffffffffu, sum, o);
        sq  += __shfl_xor_sync(0xffffffffu, sq, o);
    }
    if ((t & 31) == 0) { rs[t >> 5] = sum; rq[t >> 5] = sq; }
    __syncthreads();
    if (t < 32) {
        float s2 = (t < 8) ? rs[t] : 0.f;
        float q2 = (t < 8) ? rq[t] : 0.f;
#pragma unroll
        for (int o = 4; o > 0; o >>= 1) {
            s2 += __shfl_xor_sync(0xffffffffu, s2, o);
            q2 += __shfl_xor_sync(0xffffffffu, q2, o);
        }
        if (t == 0) { rs[0] = s2; rq[0] = q2; }
    }
    __syncthreads();
    const float mean = rs[0] * (1.0f / 768.0f);
    float var = rq[0] * (1.0f / 768.0f) - mean * mean;
    const float rstd = rsqrtf(fmaxf(var, 0.f) + 1e-12f);
#pragma unroll
    for (int j = 0; j < 3; ++j) {
        int i = t + j * 256;
        float y = (x[j] - mean) * rstd * gamma[i] + beta[i];
        size_t idx = (size_t)r * D_ + i;
        out[idx] = y;
        __nv_bfloat16 h = __float2bfloat16(y);
        ohi[idx] = h;
        olo[idx] = __float2bfloat16(y - __bfloat162float(h));
    }
}

// ---------------- tensor-core block-sparse flash attention ----------------
// grid (78, H, B), 128 thr. Q/K/V from fused [T,2304] bf16 hi/lo planes.
// warp w owns q rows w*16..w*16+15. smem tiles padded to 72 elems/row (144B).
__global__ __launch_bounds__(128, 3) void attn_tc_kernel(
    const __nv_bfloat16* __restrict__ qkvh, const __nv_bfloat16* __restrict__ qkvl,
    const float* __restrict__ mask)
{
    extern __shared__ char smraw[];
    const uint32_t su = s2u(smraw);
    const uint32_t QH = su, QL = su + 9216, KH = su + 18432, KL = su + 27648,
                   VH = su + 36864, VL = su + 46080;

    const int b = blockIdx.z, hh = blockIdx.y, ib = blockIdx.x;
    const int tid = threadIdx.x, warp = tid >> 5, lane = tid & 31;

    int qb, t0 = 0, e = 0, slice = 0;
    bool edge;
    if (ib < 62) { qb = ib + 1; edge = false; }
    else {
        edge = true;
        int xx = ib - 62;
        e = xx >> 3; slice = xx & 7;
        qb = e ? (NB_ - 1) : 0;
        t0 = slice * 8;
    }

    const int rrow = tid >> 1, half = tid & 1;
    // load Q tile (hi+lo)
    {
        const size_t gq = (size_t)(b * S_ + qb * 64 + rrow) * NQKV + hh * 64 + half * 32;
        const uint4* s0 = (const uint4*)(qkvh + gq);
        const uint4* s1 = (const uint4*)(qkvl + gq);
        uint4* d0 = (uint4*)(smraw + rrow * 144 + half * 64);
        uint4* d1 = (uint4*)(smraw + 9216 + rrow * 144 + half * 64);
#pragma unroll
        for (int j = 0; j < 4; ++j) { d0[j] = s0[j]; d1[j] = s1[j]; }
    }

    float Sf[8][4], Of[8][4];
#pragma unroll
    for (int f = 0; f < 8; ++f)
#pragma unroll
        for (int r = 0; r < 4; ++r) Of[f][r] = 0.f;
    float m0 = -1e30f, m1 = -1e30f, l0 = 0.f, l1 = 0.f;

    const uint32_t lr15 = (lane & 15);
    const uint32_t hb = (lane >> 4);

    for (int kt = 0; kt < 8; ++kt) {
        const int kb = edge ? (t0 + kt) : g_gi[qb * 8 + kt];
        __syncthreads();
        {
            const size_t gk = (size_t)(b * S_ + kb * 64 + rrow) * NQKV + hh * 64 + half * 32;
            const uint4* kh = (const uint4*)(qkvh + gk + 768);
            const uint4* kl = (const uint4*)(qkvl + gk + 768);
            const uint4* vh = (const uint4*)(qkvh + gk + 1536);
            const uint4* vl = (const uint4*)(qkvl + gk + 1536);
            const int off = rrow * 144 + half * 64;
            uint4* dkh = (uint4*)(smraw + 18432 + off);
            uint4* dkl = (uint4*)(smraw + 27648 + off);
            uint4* dvh = (uint4*)(smraw + 36864 + off);
            uint4* dvl = (uint4*)(smraw + 46080 + off);
#pragma unroll
            for (int j = 0; j < 4; ++j) { dkh[j] = kh[j]; dkl[j] = kl[j]; dvh[j] = vh[j]; dvl[j] = vl[j]; }
        }
        __syncthreads();

        // ---- S = Q K^T (bf16x3) ----
#pragma unroll
        for (int f = 0; f < 8; ++f)
#pragma unroll
            for (int r = 0; r < 4; ++r) Sf[f][r] = 0.f;
#pragma unroll
        for (int ks = 0; ks < 4; ++ks) {
            const uint32_t colb = ks * 32 + hb * 16;
            const uint32_t qoff = (warp * 16 + lr15) * 144 + colb;
            uint32_t qh[4], ql[4];
            ldsm4a(qh, QH + qoff);
            ldsm4a(ql, QL + qoff);
#pragma unroll
            for (int np = 0; np < 4; ++np) {
                const uint32_t koff = (np * 16 + lr15) * 144 + colb;
                uint32_t kh[4], kl[4];
                ldsm4a(kh, KH + koff);
                ldsm4a(kl, KL + koff);
#pragma unroll
                for (int j = 0; j < 2; ++j) {
                    mma16816(Sf[np * 2 + j], qh, kh[j], kh[j + 2]);
                    mma16816(Sf[np * 2 + j], qh, kl[j], kl[j + 2]);
                    mma16816(Sf[np * 2 + j], ql, kh[j], kh[j + 2]);
                }
            }
        }

        // ---- mask + online softmax ----
        const float* mrow = mask + (size_t)b * S_ + kb * 64;
        float t0m = -1e30f, t1m = -1e30f;
#pragma unroll
        for (int f = 0; f < 8; ++f) {
            const int c = f * 8 + 2 * (lane & 3);
            const float2 mk = *(const float2*)(mrow + c);
            Sf[f][0] = Sf[f][0] * 0.125f - 1e9f * (1.f - mk.x);
            Sf[f][1] = Sf[f][1] * 0.125f - 1e9f * (1.f - mk.y);
            Sf[f][2] = Sf[f][2] * 0.125f - 1e9f * (1.f - mk.x);
            Sf[f][3] = Sf[f][3] * 0.125f - 1e9f * (1.f - mk.y);
            t0m = fmaxf(t0m, fmaxf(Sf[f][0], Sf[f][1]));
            t1m = fmaxf(t1m, fmaxf(Sf[f][2], Sf[f][3]));
        }
        t0m = fmaxf(t0m, __shfl_xor_sync(0xffffffffu, t0m, 1));
        t0m = fmaxf(t0m, __shfl_xor_sync(0xffffffffu, t0m, 2));
        t1m = fmaxf(t1m, __shfl_xor_sync(0xffffffffu, t1m, 1));
        t1m = fmaxf(t1m, __shfl_xor_sync(0xffffffffu, t1m, 2));
        const float mn0 = fmaxf(m0, t0m), mn1 = fmaxf(m1, t1m);
        const float cr0 = __expf(m0 - mn0), cr1 = __expf(m1 - mn1);
        float ps0 = 0.f, ps1 = 0.f;
#pragma unroll
        for (int f = 0; f < 8; ++f) {
            Sf[f][0] = __expf(Sf[f][0] - mn0);
            Sf[f][1] = __expf(Sf[f][1] - mn0);
            Sf[f][2] = __expf(Sf[f][2] - mn1);
            Sf[f][3] = __expf(Sf[f][3] - mn1);
            ps0 += Sf[f][0] + Sf[f][1];
            ps1 += Sf[f][2] + Sf[f][3];
        }
        ps0 += __shfl_xor_sync(0xffffffffu, ps0, 1);
        ps0 += __shfl_xor_sync(0xffffffffu, ps0, 2);
        ps1 += __shfl_xor_sync(0xffffffffu, ps1, 1);
        ps1 += __shfl_xor_sync(0xffffffffu, ps1, 2);
        l0 = l0 * cr0 + ps0; m0 = mn0;
        l1 = l1 * cr1 + ps1; m1 = mn1;
#pragma unroll
        for (int f = 0; f < 8; ++f) {
            Of[f][0] *= cr0; Of[f][1] *= cr0; Of[f][2] *= cr1; Of[f][3] *= cr1;
        }

        // ---- P frags (bf16 hi + lo residual), C->A identity ----
        uint32_t ph[4][4], pl[4][4];
#pragma unroll
        for (int j2 = 0; j2 < 4; ++j2) {
            const float* A = Sf[2 * j2];
            const float* Bq = Sf[2 * j2 + 1];
            float la, lb;
            __nv_bfloat162 t;
            t.x = __float2bfloat16(A[0]); t.y = __float2bfloat16(A[1]);
            la = A[0] - __bfloat162float(t.x); lb = A[1] - __bfloat162float(t.y);
            ph[j2][0] = *(uint32_t*)&t; pl[j2][0] = packbf2(la, lb);
            t.x = __float2bfloat16(A[2]); t.y = __float2bfloat16(A[3]);
            la = A[2] - __bfloat162float(t.x); lb = A[3] - __bfloat162float(t.y);
            ph[j2][1] = *(uint32_t*)&t; pl[j2][1] = packbf2(la, lb);
            t.x = __float2bfloat16(Bq[0]); t.y = __float2bfloat16(Bq[1]);
            la = Bq[0] - __bfloat162float(t.x); lb = Bq[1] - __bfloat162float(t.y);
            ph[j2][2] = *(uint32_t*)&t; pl[j2][2] = packbf2(la, lb);
            t.x = __float2bfloat16(Bq[2]); t.y = __float2bfloat16(Bq[3]);
            la = Bq[2] - __bfloat162float(t.x); lb = Bq[3] - __bfloat162float(t.y);
            ph[j2][3] = *(uint32_t*)&t; pl[j2][3] = packbf2(la, lb);
        }

        // ---- O += P V (bf16x3), V via ldmatrix.trans ----
#pragma unroll
        for (int ks2 = 0; ks2 < 4; ++ks2) {
#pragma unroll
            for (int g = 0; g < 4; ++g) {
                const uint32_t voff = (ks2 * 16 + lr15) * 144 + (g * 16 + hb * 8) * 2;
                uint32_t vh[4], vl[4];
                ldsm4t(vh, VH + voff);
                ldsm4t(vl, VL + voff);
#pragma unroll
                for (int j = 0; j < 2; ++j) {
                    mma16816(Of[g * 2 + j], ph[ks2], vh[2 * j], vh[2 * j + 1]);
                    mma16816(Of[g * 2 + j], ph[ks2], vl[2 * j], vl[2 * j + 1]);
                    mma16816(Of[g * 2 + j], pl[ks2], vh[2 * j], vh[2 * j + 1]);
                }
            }
        }
    }

    const int r0 = warp * 16 + (lane >> 2);
    if (!edge) {
        const float inv0 = 1.f / l0, inv1 = 1.f / l1;
        const size_t tk0 = (size_t)(b * S_ + qb * 64 + r0) * D_ + hh * 64;
        const size_t tk1 = tk0 + 8 * D_;
#pragma unroll
        for (int f = 0; f < 8; ++f) {
            const int c = f * 8 + 2 * (lane & 3);
            float v0 = Of[f][0] * inv0, v1 = Of[f][1] * inv0;
            float v2 = Of[f][2] * inv1, v3 = Of[f][3] * inv1;
            __nv_bfloat162 h01, h23, l01, l23;
            h01.x = __float2bfloat16(v0); h01.y = __float2bfloat16(v1);
            l01.x = __float2bfloat16(v0 - __bfloat162float(h01.x));
            l01.y = __float2bfloat16(v1 - __bfloat162float(h01.y));
            h23.x = __float2bfloat16(v2); h23.y = __float2bfloat16(v3);
            l23.x = __float2bfloat16(v2 - __bfloat162float(h23.x));
            l23.y = __float2bfloat16(v3 - __bfloat162float(h23.y));
            *(__nv_bfloat162*)(g_chi + tk0 + c) = h01;
            *(__nv_bfloat162*)(g_clo + tk0 + c) = l01;
            *(__nv_bfloat162*)(g_chi + tk1 + c) = h23;
            *(__nv_bfloat162*)(g_clo + tk1 + c) = l23;
        }
    } else {
        float* base = g_part + ((size_t)((((b * H_ + hh) * 2 + e) * 8 + slice) * 64)) * 66;
        float* pp0 = base + (size_t)r0 * 66;
        float* pp1 = base + (size_t)(r0 + 8) * 66;
#pragma unroll
        for (int f = 0; f < 8; ++f) {
            const int c = f * 8 + 2 * (lane & 3);
            pp0[c] = Of[f][0]; pp0[c + 1] = Of[f][1];
            pp1[c] = Of[f][2]; pp1[c + 1] = Of[f][3];
        }
        if ((lane & 3) == 0) {
            pp0[64] = m0; pp0[65] = l0;
            pp1[64] = m1; pp1[65] = l1;
        }
    }
}

// merge the 8 partial slices for each edge block row
__global__ __launch_bounds__(256) void merge_kernel() {
    const int e = blockIdx.x, hh = blockIdx.y, b = blockIdx.z;
    const int tid = threadIdx.x;
    const int r = tid >> 2, t4 = tid & 3;
    const size_t base = ((size_t)(((b * H_ + hh) * 2 + e) * 8)) * 64 * 66;

    float M = -1e30f;
#pragma unroll
    for (int s = 0; s < 8; ++s) M = fmaxf(M, g_part[base + ((size_t)s * 64 + r) * 66 + 64]);
    float L = 0.f, acc[16];
#pragma unroll
    for (int i = 0; i < 16; ++i) acc[i] = 0.f;
#pragma unroll
    for (int s = 0; s < 8; ++s) {
        const float* pp = g_part + base + ((size_t)s * 64 + r) * 66;
        const float w = __expf(pp[64] - M);
        L += pp[65] * w;
#pragma unroll
        for (int i = 0; i < 16; ++i) acc[i] += pp[t4 * 16 + i] * w;
    }
    const float inv = 1.0f / L;
    const int qb = e ? (NB_ - 1) : 0;
    const size_t idx = ((size_t)(b * S_ + qb * 64 + r)) * D_ + hh * 64 + t4 * 16;
#pragma unroll
    for (int i = 0; i < 16; ++i) {
        float vv = acc[i] * inv;
        __nv_bfloat16 h = __float2bfloat16(vv);
        g_chi[idx + i] = h;
        g_clo[idx + i] = __float2bfloat16(vv - __bfloat162float(h));
    }
}

// ---------------- classifier ----------------
__global__ void cls1_kernel(const float* __restrict__ h, const float* __restrict__ w,
                            const float* __restrict__ bias, float* __restrict__ out) {
    int gid = blockIdx.x * blockDim.x + threadIdx.x;
    if (gid >= 2 * 512) return;
    int b = gid >> 9, n = gid & 511;
    const float* hrow = h + (size_t)b * S_ * D_;
    float s = 0.f;
    for (int k2 = 0; k2 < D_; ++k2) s += hrow[k2] * w[(size_t)k2 * 512 + n];
    out[gid] = fmaxf(s + bias[n], 0.f);
}
__global__ void cls2_kernel(const float* __restrict__ rin, const float* __restrict__ w,
                            const float* __restrict__ bias, float* __restrict__ out) {
    int gid = blockIdx.x * blockDim.x + threadIdx.x;
    if (gid >= 2 * TGT_) return;
    int b = gid >> 10, n = gid & 1023;
    float s = 0.f;
    for (int k2 = 0; k2 < 512; ++k2) s += rin[b * 512 + k2] * w[(size_t)k2 * TGT_ + n];
    out[gid] = s + bias[n];
}

// ---------------- host ----------------
typedef CUresult (*EncFn)(CUtensorMap*, CUtensorMapDataType, cuuint32_t, void*,
                          const cuuint64_t*, const cuuint64_t*, const cuuint32_t*, const cuuint32_t*,
                          CUtensorMapInterleave, CUtensorMapSwizzle, CUtensorMapL2promotion,
                          CUtensorMapFloatOOBfill);

extern "C" void kernel_launch(void* const* d_in, const int* in_sizes, int n_in,
                              void* d_out, int out_size)
{
    const float* x        = (const float*)d_in[0];
    const float* mask     = (const float*)d_in[1];
    const float* proj_b   = (const float*)d_in[3];
    const float* pos_emb  = (const float*)d_in[4];
    const float* tok_emb  = (const float*)d_in[5];
    const float* emb_g    = (const float*)d_in[6];
    const float* emb_b    = (const float*)d_in[7];
    const float* bq_all   = (const float*)d_in[9];
    const float* bk_all   = (const float*)d_in[11];
    const float* bv_all   = (const float*)d_in[13];
    const float* bo_all   = (const float*)d_in[15];
    const float* ln1g_all = (const float*)d_in[16];
    const float* ln1b_all = (const float*)d_in[17];
    const float* bi_all   = (const float*)d_in[19];
    const float* bo2_all  = (const float*)d_in[21];
    const float* ln2g_all = (const float*)d_in[22];
    const float* ln2b_all = (const float*)d_in[23];
    const float* cls_w1   = (const float*)d_in[24];
    const float* cls_b1   = (const float*)d_in[25];
    const float* cls_w2   = (const float*)d_in[26];
    const float* cls_b2   = (const float*)d_in[27];
    const int*   rb       = (const int*)d_in[28];
    float* out = (float*)d_out;

    float *ph, *ptmp, *pcls, *pbqkv;
    __nv_bfloat16 *pwhi, *pwlo, *pxhi, *pxlo, *phhi, *phlo, *pchi, *pclo, *pfhi, *pflo, *pqvh, *pqvl;
    cudaGetSymbolAddress((void**)&ph,   g_h);
    cudaGetSymbolAddress((void**)&ptmp, g_tmp);
    cudaGetSymbolAddress((void**)&pcls, g_cls);
    cudaGetSymbolAddress((void**)&pbqkv, g_bqkv);
    cudaGetSymbolAddress((void**)&pwhi, g_whi);
    cudaGetSymbolAddress((void**)&pwlo, g_wlo);
    cudaGetSymbolAddress((void**)&pxhi, g_xhi);
    cudaGetSymbolAddress((void**)&pxlo, g_xlo);
    cudaGetSymbolAddress((void**)&phhi, g_hhi);
    cudaGetSymbolAddress((void**)&phlo, g_hlo);
    cudaGetSymbolAddress((void**)&pchi, g_chi);
    cudaGetSymbolAddress((void**)&pclo, g_clo);
    cudaGetSymbolAddress((void**)&pfhi, g_fhi);
    cudaGetSymbolAddress((void**)&pflo, g_flo);
    cudaGetSymbolAddress((void**)&pqvh, g_qkvhi);
    cudaGetSymbolAddress((void**)&pqvl, g_qkvlo);

    EncFn enc = nullptr;
    cudaDriverEntryPointQueryResult qr;
    cudaGetDriverEntryPointByVersion("cuTensorMapEncodeTiled", (void**)&enc, 12000,
                                     cudaEnableDefault, &qr);

    auto mk2 = [&](CUtensorMap* m, void* p, uint64_t K) {
        cuuint64_t d[2] = {K, T_};
        cuuint64_t st[1] = {K * 2};
        cuuint32_t bx[2] = {64, 128}, es[2] = {1, 1};
        enc(m, CU_TENSOR_MAP_DATA_TYPE_BFLOAT16, 2, p, d, st, bx, es,
            CU_TENSOR_MAP_INTERLEAVE_NONE, CU_TENSOR_MAP_SWIZZLE_128B,
            CU_TENSOR_MAP_L2_PROMOTION_L2_128B, CU_TENSOR_MAP_FLOAT_OOB_FILL_NONE);
    };
    auto mk3 = [&](CUtensorMap* m, void* p, uint64_t K, uint64_t N, uint64_t Lz) {
        cuuint64_t d[3] = {K, N, Lz};
        cuuint64_t st[2] = {K * 2, N * K * 2};
        cuuint32_t bx[3] = {64, 128, 1}, es[3] = {1, 1, 1};
        enc(m, CU_TENSOR_MAP_DATA_TYPE_BFLOAT16, 3, p, d, st, bx, es,
            CU_TENSOR_MAP_INTERLEAVE_NONE, CU_TENSOR_MAP_SWIZZLE_128B,
            CU_TENSOR_MAP_L2_PROMOTION_L2_128B, CU_TENSOR_MAP_FLOAT_OOB_FILL_NONE);
    };

    CUtensorMap mxh, mxl, mhh, mhl, mch, mcl, mfh, mfl;
    CUtensorMap mpjh, mpjl, mqkvh, mqkvl, moh, mol, mih, mil, m2h, m2l;
    mk2(&mxh, pxhi, IN_); mk2(&mxl, pxlo, IN_);
    mk2(&mhh, phhi, D_);  mk2(&mhl, phlo, D_);
    mk2(&mch, pchi, D_);  mk2(&mcl, pclo, D_);
    mk2(&mfh, pfhi, FF_); mk2(&mfl, pflo, FF_);
    mk3(&mpjh, pwhi + OFF_PROJ, IN_, D_, 1);   mk3(&mpjl, pwlo + OFF_PROJ, IN_, D_, 1);
    mk3(&mqkvh, pwhi + OFF_QKV, D_, NQKV, L_); mk3(&mqkvl, pwlo + OFF_QKV, D_, NQKV, L_);
    mk3(&moh, pwhi + OFF_WO, D_, D_, L_);      mk3(&mol, pwlo + OFF_WO, D_, D_, L_);
    mk3(&mih, pwhi + OFF_WI, D_, FF_, L_);     mk3(&mil, pwlo + OFF_WI, D_, FF_, L_);
    mk3(&m2h, pwhi + OFF_WO2, FF_, D_, L_);    mk3(&m2l, pwlo + OFF_WO2, FF_, D_, L_);

    cudaFuncSetAttribute(tgemm_kernel<false, false, false, true>,
                         cudaFuncAttributeMaxDynamicSharedMemorySize, GEMM_SMEM);
    cudaFuncSetAttribute(tgemm_kernel<false, false, true, false>,
                         cudaFuncAttributeMaxDynamicSharedMemorySize, GEMM_SMEM);
    cudaFuncSetAttribute(tgemm_kernel<false, true, false, true>,
                         cudaFuncAttributeMaxDynamicSharedMemorySize, GEMM_SMEM);
    cudaFuncSetAttribute(tgemm_kernel<true, false, true, false>,
                         cudaFuncAttributeMaxDynamicSharedMemorySize, GEMM_SMEM);
    cudaFuncSetAttribute(attn_tc_kernel,
                         cudaFuncAttributeMaxDynamicSharedMemorySize, ATTN_SMEM);

    // prep
    dim3 tb(32, 8);
    tsplit_kernel<<<dim3(D_ / 32, IN_ / 32, 1), tb>>>((const float*)d_in[2], pwhi + OFF_PROJ, pwlo + OFF_PROJ, IN_, D_, IN_ * D_);
    tsplit_kernel<<<dim3(D_ / 32, D_ / 32, L_), tb>>>((const float*)d_in[8],  pwhi + OFF_QKV,               pwlo + OFF_QKV,               D_, D_, NQKV * D_);
    tsplit_kernel<<<dim3(D_ / 32, D_ / 32, L_), tb>>>((const float*)d_in[10], pwhi + OFF_QKV + 768 * 768,   pwlo + OFF_QKV + 768 * 768,   D_, D_, NQKV * D_);
    tsplit_kernel<<<dim3(D_ / 32, D_ / 32, L_), tb>>>((const float*)d_in[12], pwhi + OFF_QKV + 2 * 768 * 768, pwlo + OFF_QKV + 2 * 768 * 768, D_, D_, NQKV * D_);
    tsplit_kernel<<<dim3(D_ / 32, D_ / 32, L_), tb>>>((const float*)d_in[14], pwhi + OFF_WO, pwlo + OFF_WO, D_, D_, D_ * D_);
    tsplit_kernel<<<dim3(FF_ / 32, D_ / 32, L_), tb>>>((const float*)d_in[18], pwhi + OFF_WI, pwlo + OFF_WI, D_, FF_, D_ * FF_);
    tsplit_kernel<<<dim3(D_ / 32, FF_ / 32, L_), tb>>>((const float*)d_in[20], pwhi + OFF_WO2, pwlo + OFF_WO2, FF_, D_, FF_ * D_);
    split_kernel<<<(T_ * IN_ + 255) / 256, 256>>>(x, pxhi, pxlo, T_ * IN_);
    build_gi_kernel<<<1, 64>>>(rb);
    bcat_kernel<<<(L_ * NQKV + 255) / 256, 256>>>(bq_all, bk_all, bv_all);

    const dim3 gD(D_ / 128, T_ / 128);
    const dim3 gQKV(NQKV / 128, T_ / 128);
    const dim3 gF(FF_ / 128, T_ / 128);
    const dim3 gA(78, H_, B_);
    const dim3 gM(2, H_, B_);

    tgemm_kernel<false, false, false, true><<<gD, 256, GEMM_SMEM>>>(
        mxh, mxl, mpjh, mpjl, proj_b, nullptr, ptmp, nullptr, nullptr, D_, IN_, 0);
    ln_kernel<<<T_, 256>>>(ptmp, emb_g, emb_b, ph, phhi, phlo, pos_emb, tok_emb);

    for (int l = 0; l < L_; ++l) {
        tgemm_kernel<false, false, true, false><<<gQKV, 256, GEMM_SMEM>>>(
            mhh, mhl, mqkvh, mqkvl, pbqkv + (size_t)l * NQKV, nullptr,
            nullptr, pqvh, pqvl, NQKV, D_, l);

        attn_tc_kernel<<<gA, 128, ATTN_SMEM>>>(pqvh, pqvl, mask);
        merge_kernel<<<gM, 256>>>();

        tgemm_kernel<false, true, false, true><<<gD, 256, GEMM_SMEM>>>(
            mch, mcl, moh, mol, bo_all + (size_t)l * D_, ph, ptmp, nullptr, nullptr, D_, D_, l);
        ln_kernel<<<T_, 256>>>(ptmp, ln1g_all + (size_t)l * D_, ln1b_all + (size_t)l * D_,
                               ph, phhi, phlo, nullptr, nullptr);

        tgemm_kernel<true, false, true, false><<<gF, 256, GEMM_SMEM>>>(
            mhh, mhl, mih, mil, bi_all + (size_t)l * FF_, nullptr, nullptr, pfhi, pflo, FF_, D_, l);
        tgemm_kernel<false, true, false, true><<<gD, 256, GEMM_SMEM>>>(
            mfh, mfl, m2h, m2l, bo2_all + (size_t)l * D_, ph, ptmp, nullptr, nullptr, D_, FF_, l);
        ln_kernel<<<T_, 256>>>(ptmp, ln2g_all + (size_t)l * D_, ln2b_all + (size_t)l * D_,
                               ph, phhi, phlo, nullptr, nullptr);
    }

    cls1_kernel<<<4, 256>>>(ph, cls_w1, cls_b1, pcls);
    cls2_kernel<<<8, 256>>>(pcls, cls_w2, cls_b2, out);
}